// round 2
// baseline (speedup 1.0000x reference)
#include <cuda_runtime.h>

#define NMAX 100000
#define EMAX 1600000
#define GMAX 1024
#define HID  64
#define NFEAT 128

// ---------------- scratch (device globals; no allocation allowed) ------------
__device__ __align__(16) int   g_deg[NMAX];
__device__ __align__(16) float g_dinv[NMAX];
__device__ __align__(16) int   g_off[NMAX + 1];
__device__ __align__(16) int   g_fill[NMAX];
__device__ __align__(16) int   g_srcs[EMAX];
__device__ __align__(16) float g_wnorm[EMAX];
__device__ __align__(16) float g_hA[NMAX * HID];   // GEMM output
__device__ __align__(16) float g_hB[NMAX * HID];   // agg output / GEMM input
__device__ __align__(16) float g_emb[GMAX * HID];
__device__ __align__(16) int   g_cnt[GMAX];

// ---------------- setup kernels ----------------------------------------------
__global__ void init_kernel(int n) {
    int i = blockIdx.x * blockDim.x + threadIdx.x;
    if (i < n) { g_deg[i] = 1; g_fill[i] = 0; }   // deg starts at 1 for self-loop
}

__global__ void count_kernel(const int* __restrict__ ei, int E) {
    int e = blockIdx.x * blockDim.x + threadIdx.x;
    if (e < E) {
        int d = ei[E + e];                         // dst row
        atomicAdd(&g_deg[d], 1);
    }
}

__global__ void dinv_kernel(int n) {
    int i = blockIdx.x * blockDim.x + threadIdx.x;
    if (i < n) g_dinv[i] = rsqrtf((float)g_deg[i]);
}

// single-block exclusive scan of (deg-1) -> CSR offsets
__global__ void scan_kernel(int n) {
    __shared__ int part[1024];
    int tid = threadIdx.x;
    int chunk = (n + 1023) >> 10;
    int start = tid * chunk;
    int end = start + chunk; if (end > n) end = n;
    int s = 0;
    for (int i = start; i < end && start < n; i++) s += g_deg[i] - 1;
    part[tid] = (start < n) ? s : 0;
    __syncthreads();
    for (int d2 = 1; d2 < 1024; d2 <<= 1) {
        int v = 0;
        if (tid >= d2) v = part[tid - d2];
        __syncthreads();
        if (tid >= d2) part[tid] += v;
        __syncthreads();
    }
    int run = (tid == 0) ? 0 : part[tid - 1];
    for (int i = start; i < end && start < n; i++) { g_off[i] = run; run += g_deg[i] - 1; }
    if (tid == 1023) g_off[n] = part[1023];
}

__global__ void fill_kernel(const int* __restrict__ ei, int E) {
    int e = blockIdx.x * blockDim.x + threadIdx.x;
    if (e >= E) return;
    int s = ei[e];
    int d = ei[E + e];
    int pos = g_off[d] + atomicAdd(&g_fill[d], 1);
    g_srcs[pos]  = s;
    g_wnorm[pos] = g_dinv[s] * g_dinv[d];
}

// ---------------- GEMM: out[n,64] = in[n,K] @ W[K,64] ------------------------
// block = 256 threads, tile 32 rows x 64 cols
template <int K, int FROMX>
__global__ void gemm_kernel(const float* __restrict__ xin, const float* __restrict__ W, int n) {
    __shared__ float xs[32 * K];
    __shared__ float ws[K * HID];
    const float* in = FROMX ? xin : g_hB;
    float* out = g_hA;

    int row0 = blockIdx.x * 32;
    for (int i = threadIdx.x; i < K * HID; i += 256) ws[i] = W[i];
    for (int i = threadIdx.x; i < 32 * K; i += 256) {
        int r = i / K, c = i - r * K;
        int gr = row0 + r;
        xs[i] = (gr < n) ? in[gr * K + c] : 0.f;
    }
    __syncthreads();

    int r  = threadIdx.x >> 3;
    int c0 = (threadIdx.x & 7) * 8;
    float acc[8];
#pragma unroll
    for (int j = 0; j < 8; j++) acc[j] = 0.f;
#pragma unroll
    for (int k = 0; k < K; k++) {
        float a = xs[r * K + k];
#pragma unroll
        for (int j = 0; j < 8; j++) acc[j] = fmaf(a, ws[k * HID + c0 + j], acc[j]);
    }
    int gr = row0 + r;
    if (gr < n) {
#pragma unroll
        for (int j = 0; j < 8; j++) out[gr * HID + c0 + j] = acc[j];
    }
}

// ---------------- aggregation: g_hB[d] = sum_e norm * g_hA[src] + self + bias -
// one warp per destination node; 2 floats per lane
__global__ void agg_kernel(const float* __restrict__ bias, int n, int relu) {
    int warp = (blockIdx.x * blockDim.x + threadIdx.x) >> 5;
    int lane = threadIdx.x & 31;
    if (warp >= n) return;

    const float2* hv = (const float2*)g_hA;
    float di = g_dinv[warp];
    float sw = di * di;
    float2 hs = hv[warp * 32 + lane];
    float ax = hs.x * sw, ay = hs.y * sw;

    int beg = g_off[warp], end = g_off[warp + 1];
    int e = beg;
    for (; e + 2 <= end; e += 2) {
        int   s0 = g_srcs[e],     s1 = g_srcs[e + 1];
        float w0 = g_wnorm[e],    w1 = g_wnorm[e + 1];
        float2 h0 = hv[s0 * 32 + lane];
        float2 h1 = hv[s1 * 32 + lane];
        ax += w0 * h0.x + w1 * h1.x;
        ay += w0 * h0.y + w1 * h1.y;
    }
    if (e < end) {
        int s0 = g_srcs[e]; float w0 = g_wnorm[e];
        float2 h0 = hv[s0 * 32 + lane];
        ax += w0 * h0.x; ay += w0 * h0.y;
    }
    float2 b = ((const float2*)bias)[lane];
    ax += b.x; ay += b.y;
    if (relu) { ax = fmaxf(ax, 0.f); ay = fmaxf(ay, 0.f); }
    float2 o; o.x = ax; o.y = ay;
    ((float2*)g_hB)[warp * 32 + lane] = o;
}

// ---------------- pooling ----------------------------------------------------
__global__ void zero_pool_kernel(int G) {
    int i = blockIdx.x * blockDim.x + threadIdx.x;
    if (i < G * HID) g_emb[i] = 0.f;
    if (i < G) g_cnt[i] = 0;
}

__global__ void pool_kernel(const int* __restrict__ batch, int n) {
    int warp = (blockIdx.x * blockDim.x + threadIdx.x) >> 5;
    int lane = threadIdx.x & 31;
    if (warp >= n) return;
    int g = batch[warp];
    float2 v = ((const float2*)g_hB)[warp * 32 + lane];
    atomicAdd(&g_emb[g * HID + lane * 2],     v.x);
    atomicAdd(&g_emb[g * HID + lane * 2 + 1], v.y);
    if (lane == 0) atomicAdd(&g_cnt[g], 1);
}

// ---------------- head: distances to centroids, min per class ----------------
__global__ void head_kernel(const float* __restrict__ centroids,
                            const float* __restrict__ rbias,
                            float* __restrict__ out) {
    int g = blockIdx.x;
    int t = threadIdx.x;   // 64 threads
    __shared__ float e[HID];
    __shared__ float d[48];
    __shared__ float dpc[16];

    float c = (float)g_cnt[g];
    c = fmaxf(c, 1.f);
    e[t] = g_emb[g * HID + t] / c;
    __syncthreads();

    if (t < 48) {
        float acc = 0.f;
#pragma unroll
        for (int k = 0; k < HID; k++) {
            float df = e[k] - centroids[t * HID + k];
            acc = fmaf(df, df, acc);
        }
        d[t] = acc;
    }
    __syncthreads();
    if (t < 16) {
        float m = fminf(d[t * 3], fminf(d[t * 3 + 1], d[t * 3 + 2]));
        dpc[t] = m;
        out[g * 17 + t] = -m;
    }
    __syncthreads();
    if (t == 0) {
        float mm = dpc[0];
#pragma unroll
        for (int i = 1; i < 16; i++) mm = fminf(mm, dpc[i]);
        out[g * 17 + 16] = mm - rbias[0];
    }
}

// ---------------- launch -----------------------------------------------------
extern "C" void kernel_launch(void* const* d_in, const int* in_sizes, int n_in,
                              void* d_out, int out_size) {
    const float* x     = (const float*)d_in[0];
    const int*   ei    = (const int*)d_in[1];
    const int*   batch = (const int*)d_in[2];
    const float* W1    = (const float*)d_in[3];
    const float* b1    = (const float*)d_in[4];
    const float* W2    = (const float*)d_in[5];
    const float* b2    = (const float*)d_in[6];
    const float* W3    = (const float*)d_in[7];
    const float* b3    = (const float*)d_in[8];
    const float* cent  = (const float*)d_in[9];
    const float* rb    = (const float*)d_in[10];
    float* out = (float*)d_out;

    int n = in_sizes[0] / NFEAT;
    int E = in_sizes[1] / 2;
    int G = out_size / 17;

    // graph preprocessing (CSR by dst)
    init_kernel<<<(n + 255) / 256, 256>>>(n);
    count_kernel<<<(E + 255) / 256, 256>>>(ei, E);
    dinv_kernel<<<(n + 255) / 256, 256>>>(n);
    scan_kernel<<<1, 1024>>>(n);
    fill_kernel<<<(E + 255) / 256, 256>>>(ei, E);

    int gemm_blocks = (n + 31) / 32;
    int agg_blocks  = (n + 7) / 8;     // 8 warps per block, 1 warp per node

    // layer 1
    gemm_kernel<NFEAT, 1><<<gemm_blocks, 256>>>(x, W1, n);
    agg_kernel<<<agg_blocks, 256>>>(b1, n, 1);
    // layer 2
    gemm_kernel<HID, 0><<<gemm_blocks, 256>>>(nullptr, W2, n);
    agg_kernel<<<agg_blocks, 256>>>(b2, n, 1);
    // layer 3
    gemm_kernel<HID, 0><<<gemm_blocks, 256>>>(nullptr, W3, n);
    agg_kernel<<<agg_blocks, 256>>>(b3, n, 0);

    // pooling + head
    zero_pool_kernel<<<(G * HID + 255) / 256, 256>>>(G);
    pool_kernel<<<agg_blocks, 256>>>(batch, n);
    head_kernel<<<G, 64>>>(cent, rb, out);
}

// round 4
// speedup vs baseline: 1.5682x; 1.5682x over previous
#include <cuda_runtime.h>

#define NMAX 100000
#define EMAX 1600000
#define GMAX 1024
#define HID  64
#define NFEAT 128

// ---------------- scratch (device globals; no allocation allowed) ------------
__device__ __align__(16) int   g_deg[NMAX];
__device__ __align__(16) float g_dinv[NMAX];
__device__ __align__(16) int   g_off[NMAX];
__device__ __align__(16) int   g_fill[NMAX];
__device__ __align__(16) int   g_srcs[EMAX];
__device__ __align__(16) float g_wnorm[EMAX];
__device__ __align__(16) float g_hA[NMAX * HID];   // GEMM output
__device__ __align__(16) float g_hB[NMAX * HID];   // agg output / GEMM input
__device__ __align__(16) float g_emb[GMAX * HID];
__device__ __align__(16) int   g_cnt[GMAX];
__device__ int g_total;

// ---------------- setup ------------------------------------------------------
__global__ void zero_cnt_kernel(int G) {
    int i = blockIdx.x * blockDim.x + threadIdx.x;
    if (i < G) g_cnt[i] = 0;
}

__global__ void setup_kernel(const int* __restrict__ batch, int n, int G) {
    int i = blockIdx.x * blockDim.x + threadIdx.x;
    if (i < n) {
        g_deg[i] = 1;          // self-loop
        g_fill[i] = 0;
        atomicAdd(&g_cnt[batch[i]], 1);   // node count per graph
    }
    if (i < G * HID) g_emb[i] = 0.f;
    if (i == 0) g_total = 0;
}

__global__ void count_kernel(const int* __restrict__ ei, int E) {
    int e = blockIdx.x * blockDim.x + threadIdx.x;
    if (e < E) atomicAdd(&g_deg[ei[E + e]], 1);
}

// dinv + atomic CSR range allocation (order-free, replaces the serial scan)
__global__ void alloc_kernel(int n) {
    int i = blockIdx.x * blockDim.x + threadIdx.x;
    if (i < n) {
        int d = g_deg[i];
        g_dinv[i] = rsqrtf((float)d);
        g_off[i] = atomicAdd(&g_total, d - 1);
    }
}

__global__ void fill_kernel(const int* __restrict__ ei, int E) {
    int e = blockIdx.x * blockDim.x + threadIdx.x;
    if (e >= E) return;
    int s = ei[e];
    int d = ei[E + e];
    int pos = g_off[d] + atomicAdd(&g_fill[d], 1);
    g_srcs[pos]  = s;
    g_wnorm[pos] = g_dinv[s] * g_dinv[d];
}

// ---------------- GEMM: g_hA[n,64] = in[n,K] @ W[K,64] -----------------------
// block = 256 threads, tile 32 rows x 64 cols.
// FROMARG selects the input INSIDE device code (never pass __device__ symbols
// as host-side kernel args — on GB300 that silently reads the host shadow!)
template <int K, int FROMARG>
__global__ __launch_bounds__(256) void gemm_kernel(const float* __restrict__ xin,
                                                   const float* __restrict__ W, int n) {
    __shared__ float xs[32 * K];
    __shared__ float ws[K * HID];
    const float* in = FROMARG ? xin : (const float*)g_hB;
    float* out = g_hA;

    int row0 = blockIdx.x * 32;
    for (int i = threadIdx.x; i < K * HID / 4; i += 256)
        ((float4*)ws)[i] = ((const float4*)W)[i];
    for (int i = threadIdx.x; i < 32 * K / 4; i += 256) {
        int r = i / (K / 4), c = i - r * (K / 4);
        int gr = row0 + r;
        float4 v = make_float4(0.f, 0.f, 0.f, 0.f);
        if (gr < n) v = ((const float4*)in)[gr * (K / 4) + c];
        ((float4*)xs)[i] = v;
    }
    __syncthreads();

    int r  = threadIdx.x >> 3;
    int c0 = (threadIdx.x & 7) * 8;
    float acc[8];
#pragma unroll
    for (int j = 0; j < 8; j++) acc[j] = 0.f;
#pragma unroll
    for (int k = 0; k < K; k++) {
        float a = xs[r * K + k];
#pragma unroll
        for (int j = 0; j < 8; j++) acc[j] = fmaf(a, ws[k * HID + c0 + j], acc[j]);
    }
    int gr = row0 + r;
    if (gr < n) {
#pragma unroll
        for (int j = 0; j < 8; j++) out[gr * HID + c0 + j] = acc[j];
    }
}

// ---------------- aggregation ------------------------------------------------
// One warp per dst node. Half-warp edge pairing: lanes 0-15 even edges,
// lanes 16-31 odd edges; each lane owns 4 columns (float4). Combine by shfl.
// FUSEPOOL: accumulate straight into per-graph embedding (layer 3).
template <int FUSEPOOL>
__global__ __launch_bounds__(256) void agg_kernel(const float* __restrict__ bias,
                                                  const int* __restrict__ batch,
                                                  int n, int relu) {
    int warp = (blockIdx.x * blockDim.x + threadIdx.x) >> 5;
    if (warp >= n) return;
    int lane = threadIdx.x & 31;
    int half = lane >> 4;
    int sl   = lane & 15;

    const float4* hv = (const float4*)g_hA;
    float4 acc = make_float4(0.f, 0.f, 0.f, 0.f);

    int beg = g_off[warp];
    int end = beg + g_deg[warp] - 1;
    for (int e = beg + half; e < end; e += 2) {
        int   s = g_srcs[e];
        float w = g_wnorm[e];
        float4 h = hv[s * 16 + sl];
        acc.x = fmaf(w, h.x, acc.x);
        acc.y = fmaf(w, h.y, acc.y);
        acc.z = fmaf(w, h.z, acc.z);
        acc.w = fmaf(w, h.w, acc.w);
    }
    acc.x += __shfl_down_sync(0xffffffffu, acc.x, 16);
    acc.y += __shfl_down_sync(0xffffffffu, acc.y, 16);
    acc.z += __shfl_down_sync(0xffffffffu, acc.z, 16);
    acc.w += __shfl_down_sync(0xffffffffu, acc.w, 16);

    if (half == 0) {
        float di = g_dinv[warp];
        float sw = di * di;
        float4 hs = hv[warp * 16 + sl];
        float4 b  = ((const float4*)bias)[sl];
        acc.x = fmaf(sw, hs.x, acc.x) + b.x;
        acc.y = fmaf(sw, hs.y, acc.y) + b.y;
        acc.z = fmaf(sw, hs.z, acc.z) + b.z;
        acc.w = fmaf(sw, hs.w, acc.w) + b.w;
        if (relu) {
            acc.x = fmaxf(acc.x, 0.f);
            acc.y = fmaxf(acc.y, 0.f);
            acc.z = fmaxf(acc.z, 0.f);
            acc.w = fmaxf(acc.w, 0.f);
        }
        if (FUSEPOOL) {
            int g = batch[warp];
            float* dst = &g_emb[g * HID + sl * 4];
            atomicAdd(dst + 0, acc.x);
            atomicAdd(dst + 1, acc.y);
            atomicAdd(dst + 2, acc.z);
            atomicAdd(dst + 3, acc.w);
        } else {
            ((float4*)g_hB)[warp * 16 + sl] = acc;
        }
    }
}

// ---------------- head: distances to centroids, min per class ----------------
__global__ void head_kernel(const float* __restrict__ centroids,
                            const float* __restrict__ rbias,
                            float* __restrict__ out) {
    int g = blockIdx.x;
    int t = threadIdx.x;   // 64 threads
    __shared__ float e[HID];
    __shared__ float d[48];
    __shared__ float dpc[16];

    float c = (float)g_cnt[g];
    c = fmaxf(c, 1.f);
    e[t] = g_emb[g * HID + t] / c;
    __syncthreads();

    if (t < 48) {
        float acc = 0.f;
#pragma unroll
        for (int k = 0; k < HID; k++) {
            float df = e[k] - centroids[t * HID + k];
            acc = fmaf(df, df, acc);
        }
        d[t] = acc;
    }
    __syncthreads();
    if (t < 16) {
        float m = fminf(d[t * 3], fminf(d[t * 3 + 1], d[t * 3 + 2]));
        dpc[t] = m;
        out[g * 17 + t] = -m;
    }
    __syncthreads();
    if (t == 0) {
        float mm = dpc[0];
#pragma unroll
        for (int i = 1; i < 16; i++) mm = fminf(mm, dpc[i]);
        out[g * 17 + 16] = mm - rbias[0];
    }
}

// ---------------- launch -----------------------------------------------------
extern "C" void kernel_launch(void* const* d_in, const int* in_sizes, int n_in,
                              void* d_out, int out_size) {
    const float* x     = (const float*)d_in[0];
    const int*   ei    = (const int*)d_in[1];
    const int*   batch = (const int*)d_in[2];
    const float* W1    = (const float*)d_in[3];
    const float* b1    = (const float*)d_in[4];
    const float* W2    = (const float*)d_in[5];
    const float* b2    = (const float*)d_in[6];
    const float* W3    = (const float*)d_in[7];
    const float* b3    = (const float*)d_in[8];
    const float* cent  = (const float*)d_in[9];
    const float* rb    = (const float*)d_in[10];
    float* out = (float*)d_out;

    int n = in_sizes[0] / NFEAT;
    int E = in_sizes[1] / 2;
    int G = out_size / 17;

    // graph preprocessing (CSR by dst, order-free atomic allocation)
    zero_cnt_kernel<<<(G + 255) / 256, 256>>>(G);
    int setup_n = (n > G * HID) ? n : G * HID;
    setup_kernel<<<(setup_n + 255) / 256, 256>>>(batch, n, G);
    count_kernel<<<(E + 255) / 256, 256>>>(ei, E);
    alloc_kernel<<<(n + 255) / 256, 256>>>(n);
    fill_kernel<<<(E + 255) / 256, 256>>>(ei, E);

    int gemm_blocks = (n + 31) / 32;
    int agg_blocks  = (n + 7) / 8;     // 8 warps/block, 1 warp/node

    // layer 1
    gemm_kernel<NFEAT, 1><<<gemm_blocks, 256>>>(x, W1, n);
    agg_kernel<0><<<agg_blocks, 256>>>(b1, batch, n, 1);
    // layer 2
    gemm_kernel<HID, 0><<<gemm_blocks, 256>>>(nullptr, W2, n);
    agg_kernel<0><<<agg_blocks, 256>>>(b2, batch, n, 1);
    // layer 3 (aggregation fused with mean-pool accumulation)
    gemm_kernel<HID, 0><<<gemm_blocks, 256>>>(nullptr, W3, n);
    agg_kernel<1><<<agg_blocks, 256>>>(b3, batch, n, 0);

    // head
    head_kernel<<<G, 64>>>(cent, rb, out);
}

// round 5
// speedup vs baseline: 2.1579x; 1.3760x over previous
#include <cuda_runtime.h>

#define NMAX 100000
#define EMAX 1600000
#define GMAX 1024
#define HID  64
#define NFEAT 128

// ---------------- scratch (device globals; no allocation allowed) ------------
__device__ __align__(16) int   g_deg[NMAX];
__device__ __align__(16) float g_dinv[NMAX];
__device__ __align__(16) int   g_off[NMAX];
__device__ __align__(16) int   g_fill[NMAX];
__device__ __align__(16) int2  g_edge[EMAX];       // packed {src, wnorm bits}
__device__ __align__(16) float g_hA[NMAX * HID];   // GEMM output
__device__ __align__(16) float g_hB[NMAX * HID];   // agg output / GEMM input
__device__ __align__(16) float g_emb[GMAX * HID];
__device__ __align__(16) int   g_cnt[GMAX];
__device__ int g_total;

// ---------------- setup ------------------------------------------------------
__global__ void zero_cnt_kernel(int G) {
    int i = blockIdx.x * blockDim.x + threadIdx.x;
    if (i < G) g_cnt[i] = 0;
}

__global__ void setup_kernel(const int* __restrict__ batch, int n, int G) {
    int i = blockIdx.x * blockDim.x + threadIdx.x;
    if (i < n) {
        g_deg[i] = 1;          // self-loop
        g_fill[i] = 0;
        atomicAdd(&g_cnt[batch[i]], 1);   // node count per graph
    }
    if (i < G * HID) g_emb[i] = 0.f;
    if (i == 0) g_total = 0;
}

__global__ void count_kernel(const int* __restrict__ ei, int E) {
    int e = blockIdx.x * blockDim.x + threadIdx.x;
    if (e < E) atomicAdd(&g_deg[ei[E + e]], 1);
}

// dinv + atomic CSR range allocation (order-free; no serial scan)
__global__ void alloc_kernel(int n) {
    int i = blockIdx.x * blockDim.x + threadIdx.x;
    if (i < n) {
        int d = g_deg[i];
        g_dinv[i] = rsqrtf((float)d);
        g_off[i] = atomicAdd(&g_total, d - 1);
    }
}

__global__ void fill_kernel(const int* __restrict__ ei, int E) {
    int e = blockIdx.x * blockDim.x + threadIdx.x;
    if (e >= E) return;
    int s = ei[e];
    int d = ei[E + e];
    int pos = g_off[d] + atomicAdd(&g_fill[d], 1);
    int2 p;
    p.x = s;
    p.y = __float_as_int(g_dinv[s] * g_dinv[d]);
    g_edge[pos] = p;
}

// ---------------- GEMM: g_hA[n,64] = in[n,K] @ W[K,64] -----------------------
// 64-row x 64-col tile, 256 threads, 2 rows x 8 cols per thread.
// Dynamic smem (66.5KB for K=128). FROMARG selects input in DEVICE code only.
template <int K, int FROMARG>
__global__ __launch_bounds__(256) void gemm_kernel(const float* __restrict__ xin,
                                                   const float* __restrict__ W, int n) {
    constexpr int KP = K + 4;                 // pad: conflict-free a-loads
    extern __shared__ float sm[];
    float* xs = sm;                           // [64][KP]
    float* ws = sm + 64 * KP;                 // [K][64]
    const float* in = FROMARG ? xin : (const float*)g_hB;
    float* out = g_hA;

    int row0 = blockIdx.x * 64;
    for (int i = threadIdx.x; i < K * HID / 4; i += 256)
        ((float4*)ws)[i] = ((const float4*)W)[i];
    for (int i = threadIdx.x; i < 64 * (K / 4); i += 256) {
        int r = i / (K / 4), c = i - r * (K / 4);
        int gr = row0 + r;
        float4 v = make_float4(0.f, 0.f, 0.f, 0.f);
        if (gr < n) v = ((const float4*)in)[gr * (K / 4) + c];
        *(float4*)&xs[r * KP + c * 4] = v;    // KP%4==0 -> 16B aligned
    }
    __syncthreads();

    int r0 = threadIdx.x >> 3;                // 0..31
    int c0 = (threadIdx.x & 7) * 8;
    float a0c[8], a1c[8];
#pragma unroll
    for (int j = 0; j < 8; j++) { a0c[j] = 0.f; a1c[j] = 0.f; }

#pragma unroll 4
    for (int k = 0; k < K; k++) {
        float a0 = xs[r0 * KP + k];
        float a1 = xs[(r0 + 32) * KP + k];
        float4 b0 = *(const float4*)&ws[k * HID + c0];
        float4 b1 = *(const float4*)&ws[k * HID + c0 + 4];
        a0c[0] = fmaf(a0, b0.x, a0c[0]); a0c[1] = fmaf(a0, b0.y, a0c[1]);
        a0c[2] = fmaf(a0, b0.z, a0c[2]); a0c[3] = fmaf(a0, b0.w, a0c[3]);
        a0c[4] = fmaf(a0, b1.x, a0c[4]); a0c[5] = fmaf(a0, b1.y, a0c[5]);
        a0c[6] = fmaf(a0, b1.z, a0c[6]); a0c[7] = fmaf(a0, b1.w, a0c[7]);
        a1c[0] = fmaf(a1, b0.x, a1c[0]); a1c[1] = fmaf(a1, b0.y, a1c[1]);
        a1c[2] = fmaf(a1, b0.z, a1c[2]); a1c[3] = fmaf(a1, b0.w, a1c[3]);
        a1c[4] = fmaf(a1, b1.x, a1c[4]); a1c[5] = fmaf(a1, b1.y, a1c[5]);
        a1c[6] = fmaf(a1, b1.z, a1c[6]); a1c[7] = fmaf(a1, b1.w, a1c[7]);
    }

    int gr0 = row0 + r0, gr1 = gr0 + 32;
    if (gr0 < n) {
        *(float4*)&out[gr0 * HID + c0]     = make_float4(a0c[0], a0c[1], a0c[2], a0c[3]);
        *(float4*)&out[gr0 * HID + c0 + 4] = make_float4(a0c[4], a0c[5], a0c[6], a0c[7]);
    }
    if (gr1 < n) {
        *(float4*)&out[gr1 * HID + c0]     = make_float4(a1c[0], a1c[1], a1c[2], a1c[3]);
        *(float4*)&out[gr1 * HID + c0 + 4] = make_float4(a1c[4], a1c[5], a1c[6], a1c[7]);
    }
}

// ---------------- aggregation ------------------------------------------------
// One warp per dst node. Half-warp edge pairing (lanes 0-15 even edges, 16-31
// odd), 2x unrolled for MLP=2 on the gathers. Packed int2 edge records.
// FUSEPOOL: accumulate straight into per-graph embedding (layer 3).
template <int FUSEPOOL>
__global__ __launch_bounds__(256) void agg_kernel(const float* __restrict__ bias,
                                                  const int* __restrict__ batch,
                                                  int n, int relu) {
    int warp = (blockIdx.x * blockDim.x + threadIdx.x) >> 5;
    if (warp >= n) return;
    int lane = threadIdx.x & 31;
    int half = lane >> 4;
    int sl   = lane & 15;

    const float4* hv = (const float4*)g_hA;
    float4 acc = make_float4(0.f, 0.f, 0.f, 0.f);

    int beg = g_off[warp];
    int end = beg + g_deg[warp] - 1;
    int e = beg + half;
    for (; e + 2 < end; e += 4) {
        int2 p0 = g_edge[e];
        int2 p1 = g_edge[e + 2];
        float4 h0 = hv[p0.x * 16 + sl];
        float4 h1 = hv[p1.x * 16 + sl];
        float w0 = __int_as_float(p0.y);
        float w1 = __int_as_float(p1.y);
        acc.x = fmaf(w0, h0.x, fmaf(w1, h1.x, acc.x));
        acc.y = fmaf(w0, h0.y, fmaf(w1, h1.y, acc.y));
        acc.z = fmaf(w0, h0.z, fmaf(w1, h1.z, acc.z));
        acc.w = fmaf(w0, h0.w, fmaf(w1, h1.w, acc.w));
    }
    if (e < end) {
        int2 p0 = g_edge[e];
        float4 h0 = hv[p0.x * 16 + sl];
        float w0 = __int_as_float(p0.y);
        acc.x = fmaf(w0, h0.x, acc.x);
        acc.y = fmaf(w0, h0.y, acc.y);
        acc.z = fmaf(w0, h0.z, acc.z);
        acc.w = fmaf(w0, h0.w, acc.w);
    }
    acc.x += __shfl_down_sync(0xffffffffu, acc.x, 16);
    acc.y += __shfl_down_sync(0xffffffffu, acc.y, 16);
    acc.z += __shfl_down_sync(0xffffffffu, acc.z, 16);
    acc.w += __shfl_down_sync(0xffffffffu, acc.w, 16);

    if (half == 0) {
        float di = g_dinv[warp];
        float sw = di * di;
        float4 hs = hv[warp * 16 + sl];
        float4 b  = ((const float4*)bias)[sl];
        acc.x = fmaf(sw, hs.x, acc.x) + b.x;
        acc.y = fmaf(sw, hs.y, acc.y) + b.y;
        acc.z = fmaf(sw, hs.z, acc.z) + b.z;
        acc.w = fmaf(sw, hs.w, acc.w) + b.w;
        if (relu) {
            acc.x = fmaxf(acc.x, 0.f);
            acc.y = fmaxf(acc.y, 0.f);
            acc.z = fmaxf(acc.z, 0.f);
            acc.w = fmaxf(acc.w, 0.f);
        }
        if (FUSEPOOL) {
            int g = batch[warp];
            float* dst = &g_emb[g * HID + sl * 4];
            atomicAdd(dst + 0, acc.x);
            atomicAdd(dst + 1, acc.y);
            atomicAdd(dst + 2, acc.z);
            atomicAdd(dst + 3, acc.w);
        } else {
            ((float4*)g_hB)[warp * 16 + sl] = acc;
        }
    }
}

// ---------------- head: distances to centroids, min per class ----------------
__global__ void head_kernel(const float* __restrict__ centroids,
                            const float* __restrict__ rbias,
                            float* __restrict__ out) {
    int g = blockIdx.x;
    int t = threadIdx.x;   // 64 threads
    __shared__ float e[HID];
    __shared__ float d[48];
    __shared__ float dpc[16];

    float c = (float)g_cnt[g];
    c = fmaxf(c, 1.f);
    e[t] = g_emb[g * HID + t] / c;
    __syncthreads();

    if (t < 48) {
        float acc = 0.f;
#pragma unroll
        for (int k = 0; k < HID; k++) {
            float df = e[k] - centroids[t * HID + k];
            acc = fmaf(df, df, acc);
        }
        d[t] = acc;
    }
    __syncthreads();
    if (t < 16) {
        float m = fminf(d[t * 3], fminf(d[t * 3 + 1], d[t * 3 + 2]));
        dpc[t] = m;
        out[g * 17 + t] = -m;
    }
    __syncthreads();
    if (t == 0) {
        float mm = dpc[0];
#pragma unroll
        for (int i = 1; i < 16; i++) mm = fminf(mm, dpc[i]);
        out[g * 17 + 16] = mm - rbias[0];
    }
}

// ---------------- launch -----------------------------------------------------
extern "C" void kernel_launch(void* const* d_in, const int* in_sizes, int n_in,
                              void* d_out, int out_size) {
    const float* x     = (const float*)d_in[0];
    const int*   ei    = (const int*)d_in[1];
    const int*   batch = (const int*)d_in[2];
    const float* W1    = (const float*)d_in[3];
    const float* b1    = (const float*)d_in[4];
    const float* W2    = (const float*)d_in[5];
    const float* b2    = (const float*)d_in[6];
    const float* W3    = (const float*)d_in[7];
    const float* b3    = (const float*)d_in[8];
    const float* cent  = (const float*)d_in[9];
    const float* rb    = (const float*)d_in[10];
    float* out = (float*)d_out;

    int n = in_sizes[0] / NFEAT;
    int E = in_sizes[1] / 2;
    int G = out_size / 17;

    // dynamic smem sizes for the two GEMM shapes
    const int smem128 = (64 * (NFEAT + 4) + NFEAT * HID) * (int)sizeof(float);
    const int smem64  = (64 * (HID + 4)  + HID * HID)  * (int)sizeof(float);
    static int attr_done = 0;
    if (!attr_done) {
        cudaFuncSetAttribute(gemm_kernel<NFEAT, 1>,
                             cudaFuncAttributeMaxDynamicSharedMemorySize, smem128);
        cudaFuncSetAttribute(gemm_kernel<HID, 0>,
                             cudaFuncAttributeMaxDynamicSharedMemorySize, smem64);
        attr_done = 1;
    }

    // graph preprocessing (CSR by dst, order-free atomic allocation)
    zero_cnt_kernel<<<(G + 255) / 256, 256>>>(G);
    int setup_n = (n > G * HID) ? n : G * HID;
    setup_kernel<<<(setup_n + 255) / 256, 256>>>(batch, n, G);
    count_kernel<<<(E + 255) / 256, 256>>>(ei, E);
    alloc_kernel<<<(n + 255) / 256, 256>>>(n);
    fill_kernel<<<(E + 255) / 256, 256>>>(ei, E);

    int gemm_blocks = (n + 63) / 64;
    int agg_blocks  = (n + 7) / 8;     // 8 warps/block, 1 warp/node

    // layer 1
    gemm_kernel<NFEAT, 1><<<gemm_blocks, 256, smem128>>>(x, W1, n);
    agg_kernel<0><<<agg_blocks, 256>>>(b1, batch, n, 1);
    // layer 2
    gemm_kernel<HID, 0><<<gemm_blocks, 256, smem64>>>(nullptr, W2, n);
    agg_kernel<0><<<agg_blocks, 256>>>(b2, batch, n, 1);
    // layer 3 (aggregation fused with mean-pool accumulation)
    gemm_kernel<HID, 0><<<gemm_blocks, 256, smem64>>>(nullptr, W3, n);
    agg_kernel<1><<<agg_blocks, 256>>>(b3, batch, n, 0);

    // head
    head_kernel<<<G, 64>>>(cent, rb, out);
}

// round 6
// speedup vs baseline: 2.4496x; 1.1352x over previous
#include <cuda_runtime.h>

#define NMAX 100000
#define EMAX 1600000
#define GMAX 1024
#define HID  64
#define NFEAT 128

// ---------------- scratch (device globals; no allocation allowed) ------------
__device__ __align__(16) int   g_deg[NMAX];
__device__ __align__(16) float g_dinv[NMAX];
__device__ __align__(16) int   g_off[NMAX];
__device__ __align__(16) int   g_fill[NMAX];
__device__ __align__(16) int2  g_edge[EMAX];       // packed {src, wnorm bits}
__device__ __align__(16) float g_hA[NMAX * HID];   // GEMM output
__device__ __align__(16) float g_hB[NMAX * HID];   // agg output / GEMM input
__device__ __align__(16) float g_emb[GMAX * HID];
__device__ __align__(16) int   g_cnt[GMAX];
__device__ int g_total;

// ---------------- setup ------------------------------------------------------
__global__ void zero_cnt_kernel(int G) {
    int i = blockIdx.x * blockDim.x + threadIdx.x;
    if (i < G) g_cnt[i] = 0;
}

__global__ void setup_kernel(const int* __restrict__ batch, int n, int G) {
    int i = blockIdx.x * blockDim.x + threadIdx.x;
    if (i < n) {
        g_deg[i] = 1;          // self-loop
        g_fill[i] = 0;
        atomicAdd(&g_cnt[batch[i]], 1);   // node count per graph
    }
    if (i < G * HID) g_emb[i] = 0.f;
    if (i == 0) g_total = 0;
}

__global__ void count_kernel(const int* __restrict__ ei, int E) {
    int e = blockIdx.x * blockDim.x + threadIdx.x;
    if (e < E) atomicAdd(&g_deg[ei[E + e]], 1);
}

// dinv + atomic CSR range allocation (order-free; no serial scan)
__global__ void alloc_kernel(int n) {
    int i = blockIdx.x * blockDim.x + threadIdx.x;
    if (i < n) {
        int d = g_deg[i];
        g_dinv[i] = rsqrtf((float)d);
        g_off[i] = atomicAdd(&g_total, d - 1);
    }
}

__global__ void fill_kernel(const int* __restrict__ ei, int E) {
    int e = blockIdx.x * blockDim.x + threadIdx.x;
    if (e >= E) return;
    int s = ei[e];
    int d = ei[E + e];
    int pos = g_off[d] + atomicAdd(&g_fill[d], 1);
    int2 p;
    p.x = s;
    p.y = __float_as_int(g_dinv[s] * g_dinv[d]);
    g_edge[pos] = p;
}

// ---------------- GEMM: g_hA[n,64] = in[n,K] @ W[K,64] -----------------------
// 64-row x 64-col tile, 256 threads, 2 rows x 8 cols per thread.
// a-operands loaded as float4 across k. Dynamic smem. FROMARG selects the
// input in DEVICE code only (host-side __device__ symbol args are poison).
template <int K, int FROMARG>
__global__ __launch_bounds__(256) void gemm_kernel(const float* __restrict__ xin,
                                                   const float* __restrict__ W, int n) {
    constexpr int KP = K + 4;                 // pad: conflict-free a-loads
    extern __shared__ float sm[];
    float* xs = sm;                           // [64][KP]
    float* ws = sm + 64 * KP;                 // [K][64]
    const float* in = FROMARG ? xin : (const float*)g_hB;
    float* out = g_hA;

    int row0 = blockIdx.x * 64;
    for (int i = threadIdx.x; i < K * HID / 4; i += 256)
        ((float4*)ws)[i] = ((const float4*)W)[i];
    for (int i = threadIdx.x; i < 64 * (K / 4); i += 256) {
        int r = i / (K / 4), c = i - r * (K / 4);
        int gr = row0 + r;
        float4 v = make_float4(0.f, 0.f, 0.f, 0.f);
        if (gr < n) v = ((const float4*)in)[gr * (K / 4) + c];
        *(float4*)&xs[r * KP + c * 4] = v;    // KP%4==0 -> 16B aligned
    }
    __syncthreads();

    int r0 = threadIdx.x >> 3;                // 0..31
    int c0 = (threadIdx.x & 7) * 8;
    float a0c[8], a1c[8];
#pragma unroll
    for (int j = 0; j < 8; j++) { a0c[j] = 0.f; a1c[j] = 0.f; }

#pragma unroll 2
    for (int k4 = 0; k4 < K / 4; k4++) {
        float4 av0 = *(const float4*)&xs[r0 * KP + k4 * 4];
        float4 av1 = *(const float4*)&xs[(r0 + 32) * KP + k4 * 4];
        float a0s[4] = {av0.x, av0.y, av0.z, av0.w};
        float a1s[4] = {av1.x, av1.y, av1.z, av1.w};
#pragma unroll
        for (int kk = 0; kk < 4; kk++) {
            int k = k4 * 4 + kk;
            float a0 = a0s[kk], a1 = a1s[kk];
            float4 b0 = *(const float4*)&ws[k * HID + c0];
            float4 b1 = *(const float4*)&ws[k * HID + c0 + 4];
            a0c[0] = fmaf(a0, b0.x, a0c[0]); a0c[1] = fmaf(a0, b0.y, a0c[1]);
            a0c[2] = fmaf(a0, b0.z, a0c[2]); a0c[3] = fmaf(a0, b0.w, a0c[3]);
            a0c[4] = fmaf(a0, b1.x, a0c[4]); a0c[5] = fmaf(a0, b1.y, a0c[5]);
            a0c[6] = fmaf(a0, b1.z, a0c[6]); a0c[7] = fmaf(a0, b1.w, a0c[7]);
            a1c[0] = fmaf(a1, b0.x, a1c[0]); a1c[1] = fmaf(a1, b0.y, a1c[1]);
            a1c[2] = fmaf(a1, b0.z, a1c[2]); a1c[3] = fmaf(a1, b0.w, a1c[3]);
            a1c[4] = fmaf(a1, b1.x, a1c[4]); a1c[5] = fmaf(a1, b1.y, a1c[5]);
            a1c[6] = fmaf(a1, b1.z, a1c[6]); a1c[7] = fmaf(a1, b1.w, a1c[7]);
        }
    }

    int gr0 = row0 + r0, gr1 = gr0 + 32;
    if (gr0 < n) {
        *(float4*)&out[gr0 * HID + c0]     = make_float4(a0c[0], a0c[1], a0c[2], a0c[3]);
        *(float4*)&out[gr0 * HID + c0 + 4] = make_float4(a0c[4], a0c[5], a0c[6], a0c[7]);
    }
    if (gr1 < n) {
        *(float4*)&out[gr1 * HID + c0]     = make_float4(a1c[0], a1c[1], a1c[2], a1c[3]);
        *(float4*)&out[gr1 * HID + c0 + 4] = make_float4(a1c[4], a1c[5], a1c[6], a1c[7]);
    }
}

// ---------------- aggregation ------------------------------------------------
// One warp per dst node. Half-warp edge pairing (lanes 0-15 even edges, 16-31
// odd), 4x unrolled (8 edges per warp-iteration, MLP=4 on the gathers).
// FUSEPOOL: accumulate straight into per-graph embedding (layer 3).
template <int FUSEPOOL>
__global__ __launch_bounds__(256) void agg_kernel(const float* __restrict__ bias,
                                                  const int* __restrict__ batch,
                                                  int n, int relu) {
    int warp = (blockIdx.x * blockDim.x + threadIdx.x) >> 5;
    if (warp >= n) return;
    int lane = threadIdx.x & 31;
    int half = lane >> 4;
    int sl   = lane & 15;

    const float4* hv = (const float4*)g_hA;
    float4 acc = make_float4(0.f, 0.f, 0.f, 0.f);

    int beg = g_off[warp];
    int end = beg + g_deg[warp] - 1;
    int e = beg + half;
    for (; e + 6 < end; e += 8) {
        int2 p0 = g_edge[e];
        int2 p1 = g_edge[e + 2];
        int2 p2 = g_edge[e + 4];
        int2 p3 = g_edge[e + 6];
        float4 h0 = hv[p0.x * 16 + sl];
        float4 h1 = hv[p1.x * 16 + sl];
        float4 h2 = hv[p2.x * 16 + sl];
        float4 h3 = hv[p3.x * 16 + sl];
        float w0 = __int_as_float(p0.y);
        float w1 = __int_as_float(p1.y);
        float w2 = __int_as_float(p2.y);
        float w3 = __int_as_float(p3.y);
        acc.x = fmaf(w0, h0.x, fmaf(w1, h1.x, fmaf(w2, h2.x, fmaf(w3, h3.x, acc.x))));
        acc.y = fmaf(w0, h0.y, fmaf(w1, h1.y, fmaf(w2, h2.y, fmaf(w3, h3.y, acc.y))));
        acc.z = fmaf(w0, h0.z, fmaf(w1, h1.z, fmaf(w2, h2.z, fmaf(w3, h3.z, acc.z))));
        acc.w = fmaf(w0, h0.w, fmaf(w1, h1.w, fmaf(w2, h2.w, fmaf(w3, h3.w, acc.w))));
    }
    for (; e < end; e += 2) {
        int2 p0 = g_edge[e];
        float4 h0 = hv[p0.x * 16 + sl];
        float w0 = __int_as_float(p0.y);
        acc.x = fmaf(w0, h0.x, acc.x);
        acc.y = fmaf(w0, h0.y, acc.y);
        acc.z = fmaf(w0, h0.z, acc.z);
        acc.w = fmaf(w0, h0.w, acc.w);
    }
    acc.x += __shfl_down_sync(0xffffffffu, acc.x, 16);
    acc.y += __shfl_down_sync(0xffffffffu, acc.y, 16);
    acc.z += __shfl_down_sync(0xffffffffu, acc.z, 16);
    acc.w += __shfl_down_sync(0xffffffffu, acc.w, 16);

    if (half == 0) {
        float di = g_dinv[warp];
        float sw = di * di;
        float4 hs = hv[warp * 16 + sl];
        float4 b  = ((const float4*)bias)[sl];
        acc.x = fmaf(sw, hs.x, acc.x) + b.x;
        acc.y = fmaf(sw, hs.y, acc.y) + b.y;
        acc.z = fmaf(sw, hs.z, acc.z) + b.z;
        acc.w = fmaf(sw, hs.w, acc.w) + b.w;
        if (relu) {
            acc.x = fmaxf(acc.x, 0.f);
            acc.y = fmaxf(acc.y, 0.f);
            acc.z = fmaxf(acc.z, 0.f);
            acc.w = fmaxf(acc.w, 0.f);
        }
        if (FUSEPOOL) {
            int g = batch[warp];
            float* dst = &g_emb[g * HID + sl * 4];
            atomicAdd(dst + 0, acc.x);
            atomicAdd(dst + 1, acc.y);
            atomicAdd(dst + 2, acc.z);
            atomicAdd(dst + 3, acc.w);
        } else {
            ((float4*)g_hB)[warp * 16 + sl] = acc;
        }
    }
}

// ---------------- head: distances to centroids, min per class ----------------
__global__ void head_kernel(const float* __restrict__ centroids,
                            const float* __restrict__ rbias,
                            float* __restrict__ out) {
    int g = blockIdx.x;
    int t = threadIdx.x;   // 64 threads
    __shared__ float e[HID];
    __shared__ float d[48];
    __shared__ float dpc[16];

    float c = (float)g_cnt[g];
    c = fmaxf(c, 1.f);
    e[t] = g_emb[g * HID + t] / c;
    __syncthreads();

    if (t < 48) {
        float acc = 0.f;
#pragma unroll
        for (int k = 0; k < HID; k++) {
            float df = e[k] - centroids[t * HID + k];
            acc = fmaf(df, df, acc);
        }
        d[t] = acc;
    }
    __syncthreads();
    if (t < 16) {
        float m = fminf(d[t * 3], fminf(d[t * 3 + 1], d[t * 3 + 2]));
        dpc[t] = m;
        out[g * 17 + t] = -m;
    }
    __syncthreads();
    if (t == 0) {
        float mm = dpc[0];
#pragma unroll
        for (int i = 1; i < 16; i++) mm = fminf(mm, dpc[i]);
        out[g * 17 + 16] = mm - rbias[0];
    }
}

// ---------------- launch -----------------------------------------------------
extern "C" void kernel_launch(void* const* d_in, const int* in_sizes, int n_in,
                              void* d_out, int out_size) {
    const float* x     = (const float*)d_in[0];
    const int*   ei    = (const int*)d_in[1];
    const int*   batch = (const int*)d_in[2];
    const float* W1    = (const float*)d_in[3];
    const float* b1    = (const float*)d_in[4];
    const float* W2    = (const float*)d_in[5];
    const float* b2    = (const float*)d_in[6];
    const float* W3    = (const float*)d_in[7];
    const float* b3    = (const float*)d_in[8];
    const float* cent  = (const float*)d_in[9];
    const float* rb    = (const float*)d_in[10];
    float* out = (float*)d_out;

    int n = in_sizes[0] / NFEAT;
    int E = in_sizes[1] / 2;
    int G = out_size / 17;

    const int smem128 = (64 * (NFEAT + 4) + NFEAT * HID) * (int)sizeof(float);
    const int smem64  = (64 * (HID + 4)  + HID * HID)  * (int)sizeof(float);

    static cudaStream_t s2;
    static cudaEvent_t ev_fork, ev_join;
    static int init_done = 0;
    if (!init_done) {
        cudaFuncSetAttribute(gemm_kernel<NFEAT, 1>,
                             cudaFuncAttributeMaxDynamicSharedMemorySize, smem128);
        cudaFuncSetAttribute(gemm_kernel<HID, 0>,
                             cudaFuncAttributeMaxDynamicSharedMemorySize, smem64);
        cudaStreamCreateWithFlags(&s2, cudaStreamNonBlocking);
        cudaEventCreateWithFlags(&ev_fork, cudaEventDisableTiming);
        cudaEventCreateWithFlags(&ev_join, cudaEventDisableTiming);
        init_done = 1;
    }

    int gemm_blocks = (n + 63) / 64;
    int agg_blocks  = (n + 7) / 8;     // 8 warps/block, 1 warp/node
    int setup_n = (n > G * HID) ? n : G * HID;

    // Fork: CSR build on s2 runs concurrently with layer-1 GEMM on stream 0.
    cudaEventRecord(ev_fork, 0);
    cudaStreamWaitEvent(s2, ev_fork, 0);

    zero_cnt_kernel<<<(G + 255) / 256, 256, 0, s2>>>(G);
    setup_kernel<<<(setup_n + 255) / 256, 256, 0, s2>>>(batch, n, G);
    count_kernel<<<(E + 255) / 256, 256, 0, s2>>>(ei, E);
    alloc_kernel<<<(n + 255) / 256, 256, 0, s2>>>(n);
    fill_kernel<<<(E + 255) / 256, 256, 0, s2>>>(ei, E);
    cudaEventRecord(ev_join, s2);

    // layer-1 GEMM overlaps the CSR build
    gemm_kernel<NFEAT, 1><<<gemm_blocks, 256, smem128>>>(x, W1, n);

    // join: aggregation needs both the GEMM output and the CSR
    cudaStreamWaitEvent(0, ev_join, 0);
    agg_kernel<0><<<agg_blocks, 256>>>(b1, batch, n, 1);
    // layer 2
    gemm_kernel<HID, 0><<<gemm_blocks, 256, smem64>>>(nullptr, W2, n);
    agg_kernel<0><<<agg_blocks, 256>>>(b2, batch, n, 1);
    // layer 3 (aggregation fused with mean-pool accumulation)
    gemm_kernel<HID, 0><<<gemm_blocks, 256, smem64>>>(nullptr, W3, n);
    agg_kernel<1><<<agg_blocks, 256>>>(b3, batch, n, 0);

    // head
    head_kernel<<<G, 64>>>(cent, rb, out);
}

// round 7
// speedup vs baseline: 2.6409x; 1.0781x over previous
#include <cuda_runtime.h>

#define NMAX 100000
#define EMAX 1600000
#define GMAX 1024
#define HID  64
#define NFEAT 128

// ---------------- scratch (device globals; no allocation allowed) ------------
__device__ __align__(16) int   g_deg[NMAX];
__device__ __align__(16) float g_dinv[NMAX];
__device__ __align__(16) int2  g_info[NMAX];       // {edge range offset, deg}
__device__ __align__(16) int   g_fill[NMAX];
__device__ __align__(16) int2  g_edge[EMAX];       // packed {src, wnorm bits}
__device__ __align__(16) float g_hA[NMAX * HID];   // GEMM output
__device__ __align__(16) float g_hB[NMAX * HID];   // agg output / GEMM input
__device__ __align__(16) float g_emb[GMAX * HID];
__device__ int g_total;

// ---------------- setup ------------------------------------------------------
__global__ void setup_kernel(int n, int G) {
    int i = blockIdx.x * blockDim.x + threadIdx.x;
    if (i < n) {
        g_deg[i] = 1;          // self-loop
        g_fill[i] = 0;
    }
    if (i < G * HID) g_emb[i] = 0.f;
    if (i == 0) g_total = 0;
}

__global__ void count_kernel(const int* __restrict__ ei, int E) {
    int e = blockIdx.x * blockDim.x + threadIdx.x;
    if (e < E) atomicAdd(&g_deg[ei[E + e]], 1);
}

// dinv + atomic CSR range allocation (order-free; no serial scan)
__global__ void alloc_kernel(int n) {
    int i = blockIdx.x * blockDim.x + threadIdx.x;
    if (i < n) {
        int d = g_deg[i];
        g_dinv[i] = rsqrtf((float)d);
        int2 inf;
        inf.x = atomicAdd(&g_total, d - 1);
        inf.y = d;
        g_info[i] = inf;
    }
}

__global__ void fill_kernel(const int* __restrict__ ei, int E) {
    int e = blockIdx.x * blockDim.x + threadIdx.x;
    if (e >= E) return;
    int s = ei[e];
    int d = ei[E + e];
    int pos = g_info[d].x + atomicAdd(&g_fill[d], 1);
    int2 p;
    p.x = s;
    p.y = __float_as_int(g_dinv[s] * g_dinv[d]);
    g_edge[pos] = p;
}

// ---------------- GEMM (K=128): 64-row x 64-col tile, 2 rows/thread ----------
// FROMARG selects input in DEVICE code only (host-side __device__ symbol args
// silently resolve to the host shadow on GB300 — never pass them).
template <int K, int FROMARG>
__global__ __launch_bounds__(256) void gemm_kernel(const float* __restrict__ xin,
                                                   const float* __restrict__ W, int n) {
    constexpr int KP = K + 4;
    extern __shared__ float sm[];
    float* xs = sm;                           // [64][KP]
    float* ws = sm + 64 * KP;                 // [K][64]
    const float* in = FROMARG ? xin : (const float*)g_hB;
    float* out = g_hA;

    int row0 = blockIdx.x * 64;
    for (int i = threadIdx.x; i < K * HID / 4; i += 256)
        ((float4*)ws)[i] = ((const float4*)W)[i];
    for (int i = threadIdx.x; i < 64 * (K / 4); i += 256) {
        int r = i / (K / 4), c = i - r * (K / 4);
        int gr = row0 + r;
        float4 v = make_float4(0.f, 0.f, 0.f, 0.f);
        if (gr < n) v = ((const float4*)in)[gr * (K / 4) + c];
        *(float4*)&xs[r * KP + c * 4] = v;
    }
    __syncthreads();

    int r0 = threadIdx.x >> 3;
    int c0 = (threadIdx.x & 7) * 8;
    float a0c[8], a1c[8];
#pragma unroll
    for (int j = 0; j < 8; j++) { a0c[j] = 0.f; a1c[j] = 0.f; }

#pragma unroll 2
    for (int k4 = 0; k4 < K / 4; k4++) {
        float4 av0 = *(const float4*)&xs[r0 * KP + k4 * 4];
        float4 av1 = *(const float4*)&xs[(r0 + 32) * KP + k4 * 4];
        float a0s[4] = {av0.x, av0.y, av0.z, av0.w};
        float a1s[4] = {av1.x, av1.y, av1.z, av1.w};
#pragma unroll
        for (int kk = 0; kk < 4; kk++) {
            int k = k4 * 4 + kk;
            float a0 = a0s[kk], a1 = a1s[kk];
            float4 b0 = *(const float4*)&ws[k * HID + c0];
            float4 b1 = *(const float4*)&ws[k * HID + c0 + 4];
            a0c[0] = fmaf(a0, b0.x, a0c[0]); a0c[1] = fmaf(a0, b0.y, a0c[1]);
            a0c[2] = fmaf(a0, b0.z, a0c[2]); a0c[3] = fmaf(a0, b0.w, a0c[3]);
            a0c[4] = fmaf(a0, b1.x, a0c[4]); a0c[5] = fmaf(a0, b1.y, a0c[5]);
            a0c[6] = fmaf(a0, b1.z, a0c[6]); a0c[7] = fmaf(a0, b1.w, a0c[7]);
            a1c[0] = fmaf(a1, b0.x, a1c[0]); a1c[1] = fmaf(a1, b0.y, a1c[1]);
            a1c[2] = fmaf(a1, b0.z, a1c[2]); a1c[3] = fmaf(a1, b0.w, a1c[3]);
            a1c[4] = fmaf(a1, b1.x, a1c[4]); a1c[5] = fmaf(a1, b1.y, a1c[5]);
            a1c[6] = fmaf(a1, b1.z, a1c[6]); a1c[7] = fmaf(a1, b1.w, a1c[7]);
        }
    }

    int gr0 = row0 + r0, gr1 = gr0 + 32;
    if (gr0 < n) {
        *(float4*)&out[gr0 * HID + c0]     = make_float4(a0c[0], a0c[1], a0c[2], a0c[3]);
        *(float4*)&out[gr0 * HID + c0 + 4] = make_float4(a0c[4], a0c[5], a0c[6], a0c[7]);
    }
    if (gr1 < n) {
        *(float4*)&out[gr1 * HID + c0]     = make_float4(a1c[0], a1c[1], a1c[2], a1c[3]);
        *(float4*)&out[gr1 * HID + c0 + 4] = make_float4(a1c[4], a1c[5], a1c[6], a1c[7]);
    }
}

// ---------------- GEMM (K=64): 128-row x 64-col tile, 4 rows/thread ----------
__global__ __launch_bounds__(256) void gemm64_kernel(const float* __restrict__ W, int n) {
    constexpr int K = HID;
    constexpr int KP = K + 4;
    extern __shared__ float sm[];
    float* xs = sm;                           // [128][KP]
    float* ws = sm + 128 * KP;                // [K][64]
    const float* in = (const float*)g_hB;
    float* out = g_hA;

    int row0 = blockIdx.x * 128;
    for (int i = threadIdx.x; i < K * HID / 4; i += 256)
        ((float4*)ws)[i] = ((const float4*)W)[i];
    for (int i = threadIdx.x; i < 128 * (K / 4); i += 256) {
        int r = i / (K / 4), c = i - r * (K / 4);
        int gr = row0 + r;
        float4 v = make_float4(0.f, 0.f, 0.f, 0.f);
        if (gr < n) v = ((const float4*)in)[gr * (K / 4) + c];
        *(float4*)&xs[r * KP + c * 4] = v;
    }
    __syncthreads();

    int r0 = threadIdx.x >> 3;                // 0..31
    int c0 = (threadIdx.x & 7) * 8;
    float acc[4][8];
#pragma unroll
    for (int q = 0; q < 4; q++)
#pragma unroll
        for (int j = 0; j < 8; j++) acc[q][j] = 0.f;

#pragma unroll 2
    for (int k4 = 0; k4 < K / 4; k4++) {
        float a[4][4];
#pragma unroll
        for (int q = 0; q < 4; q++) {
            float4 av = *(const float4*)&xs[(r0 + q * 32) * KP + k4 * 4];
            a[q][0] = av.x; a[q][1] = av.y; a[q][2] = av.z; a[q][3] = av.w;
        }
#pragma unroll
        for (int kk = 0; kk < 4; kk++) {
            int k = k4 * 4 + kk;
            float4 b0 = *(const float4*)&ws[k * HID + c0];
            float4 b1 = *(const float4*)&ws[k * HID + c0 + 4];
#pragma unroll
            for (int q = 0; q < 4; q++) {
                float av = a[q][kk];
                acc[q][0] = fmaf(av, b0.x, acc[q][0]);
                acc[q][1] = fmaf(av, b0.y, acc[q][1]);
                acc[q][2] = fmaf(av, b0.z, acc[q][2]);
                acc[q][3] = fmaf(av, b0.w, acc[q][3]);
                acc[q][4] = fmaf(av, b1.x, acc[q][4]);
                acc[q][5] = fmaf(av, b1.y, acc[q][5]);
                acc[q][6] = fmaf(av, b1.z, acc[q][6]);
                acc[q][7] = fmaf(av, b1.w, acc[q][7]);
            }
        }
    }

#pragma unroll
    for (int q = 0; q < 4; q++) {
        int gr = row0 + r0 + q * 32;
        if (gr < n) {
            *(float4*)&out[gr * HID + c0]     = make_float4(acc[q][0], acc[q][1], acc[q][2], acc[q][3]);
            *(float4*)&out[gr * HID + c0 + 4] = make_float4(acc[q][4], acc[q][5], acc[q][6], acc[q][7]);
        }
    }
}

// ---------------- aggregation ------------------------------------------------
// Half-warp per dst node (warp covers nodes 2w, 2w+1). 16 lanes x float4 =
// full 64-dim row. 4x-unrolled edge loop (MLP=4 per half, 8 per warp).
// FUSEPOOL: accumulate straight into per-graph embedding (layer 3).
template <int FUSEPOOL>
__global__ __launch_bounds__(256) void agg_kernel(const float* __restrict__ bias,
                                                  const int* __restrict__ batch,
                                                  int n, int relu) {
    int warp = (blockIdx.x * blockDim.x + threadIdx.x) >> 5;
    int lane = threadIdx.x & 31;
    int half = lane >> 4;
    int sl   = lane & 15;
    int node = warp * 2 + half;
    if (node >= n) return;

    const float4* hv = (const float4*)g_hA;
    float4 acc = make_float4(0.f, 0.f, 0.f, 0.f);

    int2 inf = g_info[node];
    int beg = inf.x;
    int end = beg + inf.y - 1;
    int e = beg;
    for (; e + 3 < end; e += 4) {
        int2 p0 = g_edge[e];
        int2 p1 = g_edge[e + 1];
        int2 p2 = g_edge[e + 2];
        int2 p3 = g_edge[e + 3];
        float4 h0 = hv[p0.x * 16 + sl];
        float4 h1 = hv[p1.x * 16 + sl];
        float4 h2 = hv[p2.x * 16 + sl];
        float4 h3 = hv[p3.x * 16 + sl];
        float w0 = __int_as_float(p0.y);
        float w1 = __int_as_float(p1.y);
        float w2 = __int_as_float(p2.y);
        float w3 = __int_as_float(p3.y);
        acc.x = fmaf(w0, h0.x, fmaf(w1, h1.x, fmaf(w2, h2.x, fmaf(w3, h3.x, acc.x))));
        acc.y = fmaf(w0, h0.y, fmaf(w1, h1.y, fmaf(w2, h2.y, fmaf(w3, h3.y, acc.y))));
        acc.z = fmaf(w0, h0.z, fmaf(w1, h1.z, fmaf(w2, h2.z, fmaf(w3, h3.z, acc.z))));
        acc.w = fmaf(w0, h0.w, fmaf(w1, h1.w, fmaf(w2, h2.w, fmaf(w3, h3.w, acc.w))));
    }
    for (; e < end; e++) {
        int2 p0 = g_edge[e];
        float4 h0 = hv[p0.x * 16 + sl];
        float w0 = __int_as_float(p0.y);
        acc.x = fmaf(w0, h0.x, acc.x);
        acc.y = fmaf(w0, h0.y, acc.y);
        acc.z = fmaf(w0, h0.z, acc.z);
        acc.w = fmaf(w0, h0.w, acc.w);
    }

    float di = g_dinv[node];
    float sw = di * di;
    float4 hs = hv[node * 16 + sl];
    float4 b  = ((const float4*)bias)[sl];
    acc.x = fmaf(sw, hs.x, acc.x) + b.x;
    acc.y = fmaf(sw, hs.y, acc.y) + b.y;
    acc.z = fmaf(sw, hs.z, acc.z) + b.z;
    acc.w = fmaf(sw, hs.w, acc.w) + b.w;
    if (relu) {
        acc.x = fmaxf(acc.x, 0.f);
        acc.y = fmaxf(acc.y, 0.f);
        acc.z = fmaxf(acc.z, 0.f);
        acc.w = fmaxf(acc.w, 0.f);
    }
    if (FUSEPOOL) {
        int g = batch[node];
        float* dst = &g_emb[g * HID + sl * 4];
        atomicAdd(dst + 0, acc.x);
        atomicAdd(dst + 1, acc.y);
        atomicAdd(dst + 2, acc.z);
        atomicAdd(dst + 3, acc.w);
    } else {
        ((float4*)g_hB)[node * 16 + sl] = acc;
    }
}

// ---------------- head: mean + centroid distances, min per class -------------
// batch is sorted, so graph node-counts come from two binary searches.
__global__ void head_kernel(const int* __restrict__ batch, int n,
                            const float* __restrict__ centroids,
                            const float* __restrict__ rbias,
                            float* __restrict__ out) {
    int g = blockIdx.x;
    int t = threadIdx.x;   // 64 threads
    __shared__ float e[HID];
    __shared__ float d[48];
    __shared__ float dpc[16];
    __shared__ float inv_cnt;

    if (t == 0) {
        int lo = 0, hi = n;
        while (lo < hi) { int m = (lo + hi) >> 1; if (batch[m] < g) lo = m + 1; else hi = m; }
        int a = lo;
        lo = 0; hi = n;
        while (lo < hi) { int m = (lo + hi) >> 1; if (batch[m] <= g) lo = m + 1; else hi = m; }
        int c = lo - a;
        inv_cnt = 1.0f / (float)(c > 1 ? c : 1);
    }
    __syncthreads();

    e[t] = g_emb[g * HID + t] * inv_cnt;
    __syncthreads();

    if (t < 48) {
        float acc = 0.f;
#pragma unroll
        for (int k = 0; k < HID; k++) {
            float df = e[k] - centroids[t * HID + k];
            acc = fmaf(df, df, acc);
        }
        d[t] = acc;
    }
    __syncthreads();
    if (t < 16) {
        float m = fminf(d[t * 3], fminf(d[t * 3 + 1], d[t * 3 + 2]));
        dpc[t] = m;
        out[g * 17 + t] = -m;
    }
    __syncthreads();
    if (t == 0) {
        float mm = dpc[0];
#pragma unroll
        for (int i = 1; i < 16; i++) mm = fminf(mm, dpc[i]);
        out[g * 17 + 16] = mm - rbias[0];
    }
}

// ---------------- launch -----------------------------------------------------
extern "C" void kernel_launch(void* const* d_in, const int* in_sizes, int n_in,
                              void* d_out, int out_size) {
    const float* x     = (const float*)d_in[0];
    const int*   ei    = (const int*)d_in[1];
    const int*   batch = (const int*)d_in[2];
    const float* W1    = (const float*)d_in[3];
    const float* b1    = (const float*)d_in[4];
    const float* W2    = (const float*)d_in[5];
    const float* b2    = (const float*)d_in[6];
    const float* W3    = (const float*)d_in[7];
    const float* b3    = (const float*)d_in[8];
    const float* cent  = (const float*)d_in[9];
    const float* rb    = (const float*)d_in[10];
    float* out = (float*)d_out;

    int n = in_sizes[0] / NFEAT;
    int E = in_sizes[1] / 2;
    int G = out_size / 17;

    const int smem128 = (64 * (NFEAT + 4) + NFEAT * HID) * (int)sizeof(float);
    const int smem64  = (128 * (HID + 4) + HID * HID) * (int)sizeof(float);

    static cudaStream_t s2;
    static cudaEvent_t ev_fork, ev_join;
    static int init_done = 0;
    if (!init_done) {
        cudaFuncSetAttribute(gemm_kernel<NFEAT, 1>,
                             cudaFuncAttributeMaxDynamicSharedMemorySize, smem128);
        cudaFuncSetAttribute(gemm64_kernel,
                             cudaFuncAttributeMaxDynamicSharedMemorySize, smem64);
        cudaStreamCreateWithFlags(&s2, cudaStreamNonBlocking);
        cudaEventCreateWithFlags(&ev_fork, cudaEventDisableTiming);
        cudaEventCreateWithFlags(&ev_join, cudaEventDisableTiming);
        init_done = 1;
    }

    int gemm_blocks   = (n + 63) / 64;
    int gemm64_blocks = (n + 127) / 128;
    int agg_blocks    = (n + 15) / 16;   // 8 warps/block, 2 nodes/warp
    int setup_n = (n > G * HID) ? n : G * HID;

    // Fork: CSR build on s2 runs concurrently with layer-1 GEMM on stream 0.
    cudaEventRecord(ev_fork, 0);
    cudaStreamWaitEvent(s2, ev_fork, 0);

    setup_kernel<<<(setup_n + 255) / 256, 256, 0, s2>>>(n, G);
    count_kernel<<<(E + 255) / 256, 256, 0, s2>>>(ei, E);
    alloc_kernel<<<(n + 255) / 256, 256, 0, s2>>>(n);
    fill_kernel<<<(E + 255) / 256, 256, 0, s2>>>(ei, E);
    cudaEventRecord(ev_join, s2);

    // layer-1 GEMM overlaps the CSR build
    gemm_kernel<NFEAT, 1><<<gemm_blocks, 256, smem128>>>(x, W1, n);

    // join: aggregation needs both the GEMM output and the CSR
    cudaStreamWaitEvent(0, ev_join, 0);
    agg_kernel<0><<<agg_blocks, 256>>>(b1, batch, n, 1);
    // layer 2
    gemm64_kernel<<<gemm64_blocks, 256, smem64>>>(W2, n);
    agg_kernel<0><<<agg_blocks, 256>>>(b2, batch, n, 1);
    // layer 3 (aggregation fused with mean-pool accumulation)
    gemm64_kernel<<<gemm64_blocks, 256, smem64>>>(W3, n);
    agg_kernel<1><<<agg_blocks, 256>>>(b3, batch, n, 0);

    // head
    head_kernel<<<G, 64>>>(batch, n, cent, rb, out);
}

// round 9
// speedup vs baseline: 2.9635x; 1.1221x over previous
#include <cuda_runtime.h>
#include <cuda_fp16.h>

#define NMAX 100000
#define EMAX 1600000
#define GMAX 1024
#define HID  64
#define NFEAT 128

// ---------------- scratch (device globals; no allocation allowed) ------------
__device__ __align__(16) int    g_deg[NMAX];
__device__ __align__(16) float  g_dinv[NMAX];
__device__ __align__(16) int2   g_info[NMAX];       // {edge range offset, edge count}
__device__ __align__(16) int    g_fill[NMAX];
__device__ __align__(16) int2   g_edge[EMAX];       // packed {src, wnorm bits}
__device__ __align__(16) __half g_hA[NMAX * HID];   // GEMM output (fp16 gather source)
__device__ __align__(16) float  g_hB[NMAX * HID];   // agg output / GEMM input (fp32)
__device__ __align__(16) float  g_emb[GMAX * HID];
__device__ int g_total;

// ---------------- setup ------------------------------------------------------
__global__ void count_kernel(const int* __restrict__ ei, int E) {
    int e = blockIdx.x * blockDim.x + threadIdx.x;
    if (e < E) atomicAdd(&g_deg[ei[E + e]], 1);
}

// dinv + atomic CSR range allocation (order-free; no serial scan)
__global__ void alloc_kernel(int n) {
    int i = blockIdx.x * blockDim.x + threadIdx.x;
    if (i < n) {
        int d = g_deg[i];                 // real edge count (self-loop separate)
        g_dinv[i] = rsqrtf((float)(d + 1));
        int2 inf;
        inf.x = atomicAdd(&g_total, d);
        inf.y = d;
        g_info[i] = inf;
    }
}

__global__ void fill_kernel(const int* __restrict__ ei, int E) {
    int e = blockIdx.x * blockDim.x + threadIdx.x;
    if (e >= E) return;
    int s = ei[e];
    int d = ei[E + e];
    int pos = g_info[d].x + atomicAdd(&g_fill[d], 1);
    int2 p;
    p.x = s;
    p.y = __float_as_int(g_dinv[s] * g_dinv[d]);
    g_edge[pos] = p;
}

// helper: 8 floats -> uint4 of half2s
__device__ __forceinline__ uint4 pack8_half(const float* a) {
    __half2 h0 = __floats2half2_rn(a[0], a[1]);
    __half2 h1 = __floats2half2_rn(a[2], a[3]);
    __half2 h2 = __floats2half2_rn(a[4], a[5]);
    __half2 h3 = __floats2half2_rn(a[6], a[7]);
    uint4 o;
    o.x = *(unsigned*)&h0; o.y = *(unsigned*)&h1;
    o.z = *(unsigned*)&h2; o.w = *(unsigned*)&h3;
    return o;
}

// ---------------- GEMM (K=128): 64-row x 64-col tile, 2 rows/thread ----------
// Output stored fp16 (gather source). FROMARG selects input in DEVICE code
// only (host-side __device__ symbol args silently read the host shadow).
template <int K, int FROMARG>
__global__ __launch_bounds__(256) void gemm_kernel(const float* __restrict__ xin,
                                                   const float* __restrict__ W, int n) {
    constexpr int KP = K + 4;
    extern __shared__ float sm[];
    float* xs = sm;                           // [64][KP]
    float* ws = sm + 64 * KP;                 // [K][64]
    const float* in = FROMARG ? xin : (const float*)g_hB;

    int row0 = blockIdx.x * 64;
    for (int i = threadIdx.x; i < K * HID / 4; i += 256)
        ((float4*)ws)[i] = ((const float4*)W)[i];
    for (int i = threadIdx.x; i < 64 * (K / 4); i += 256) {
        int r = i / (K / 4), c = i - r * (K / 4);
        int gr = row0 + r;
        float4 v = make_float4(0.f, 0.f, 0.f, 0.f);
        if (gr < n) v = ((const float4*)in)[gr * (K / 4) + c];
        *(float4*)&xs[r * KP + c * 4] = v;
    }
    __syncthreads();

    int r0 = threadIdx.x >> 3;
    int c8 = threadIdx.x & 7;                 // column octet
    float a0c[8], a1c[8];
#pragma unroll
    for (int j = 0; j < 8; j++) { a0c[j] = 0.f; a1c[j] = 0.f; }

#pragma unroll 2
    for (int k4 = 0; k4 < K / 4; k4++) {
        float4 av0 = *(const float4*)&xs[r0 * KP + k4 * 4];
        float4 av1 = *(const float4*)&xs[(r0 + 32) * KP + k4 * 4];
        float a0s[4] = {av0.x, av0.y, av0.z, av0.w};
        float a1s[4] = {av1.x, av1.y, av1.z, av1.w};
#pragma unroll
        for (int kk = 0; kk < 4; kk++) {
            int k = k4 * 4 + kk;
            float a0 = a0s[kk], a1 = a1s[kk];
            float4 b0 = *(const float4*)&ws[k * HID + c8 * 8];
            float4 b1 = *(const float4*)&ws[k * HID + c8 * 8 + 4];
            a0c[0] = fmaf(a0, b0.x, a0c[0]); a0c[1] = fmaf(a0, b0.y, a0c[1]);
            a0c[2] = fmaf(a0, b0.z, a0c[2]); a0c[3] = fmaf(a0, b0.w, a0c[3]);
            a0c[4] = fmaf(a0, b1.x, a0c[4]); a0c[5] = fmaf(a0, b1.y, a0c[5]);
            a0c[6] = fmaf(a0, b1.z, a0c[6]); a0c[7] = fmaf(a0, b1.w, a0c[7]);
            a1c[0] = fmaf(a1, b0.x, a1c[0]); a1c[1] = fmaf(a1, b0.y, a1c[1]);
            a1c[2] = fmaf(a1, b0.z, a1c[2]); a1c[3] = fmaf(a1, b0.w, a1c[3]);
            a1c[4] = fmaf(a1, b1.x, a1c[4]); a1c[5] = fmaf(a1, b1.y, a1c[5]);
            a1c[6] = fmaf(a1, b1.z, a1c[6]); a1c[7] = fmaf(a1, b1.w, a1c[7]);
        }
    }

    uint4* outv = (uint4*)g_hA;
    int gr0 = row0 + r0, gr1 = gr0 + 32;
    if (gr0 < n) outv[gr0 * 8 + c8] = pack8_half(a0c);
    if (gr1 < n) outv[gr1 * 8 + c8] = pack8_half(a1c);
}

// ---------------- GEMM (K=64): 128-row x 64-col tile, 4 rows/thread ----------
__global__ __launch_bounds__(256) void gemm64_kernel(const float* __restrict__ W, int n) {
    constexpr int K = HID;
    constexpr int KP = K + 4;
    extern __shared__ float sm[];
    float* xs = sm;                           // [128][KP]
    float* ws = sm + 128 * KP;                // [K][64]
    const float* in = (const float*)g_hB;

    int row0 = blockIdx.x * 128;
    for (int i = threadIdx.x; i < K * HID / 4; i += 256)
        ((float4*)ws)[i] = ((const float4*)W)[i];
    for (int i = threadIdx.x; i < 128 * (K / 4); i += 256) {
        int r = i / (K / 4), c = i - r * (K / 4);
        int gr = row0 + r;
        float4 v = make_float4(0.f, 0.f, 0.f, 0.f);
        if (gr < n) v = ((const float4*)in)[gr * (K / 4) + c];
        *(float4*)&xs[r * KP + c * 4] = v;
    }
    __syncthreads();

    int r0 = threadIdx.x >> 3;                // 0..31
    int c8 = threadIdx.x & 7;
    float acc[4][8];
#pragma unroll
    for (int q = 0; q < 4; q++)
#pragma unroll
        for (int j = 0; j < 8; j++) acc[q][j] = 0.f;

#pragma unroll 2
    for (int k4 = 0; k4 < K / 4; k4++) {
        float a[4][4];
#pragma unroll
        for (int q = 0; q < 4; q++) {
            float4 av = *(const float4*)&xs[(r0 + q * 32) * KP + k4 * 4];
            a[q][0] = av.x; a[q][1] = av.y; a[q][2] = av.z; a[q][3] = av.w;
        }
#pragma unroll
        for (int kk = 0; kk < 4; kk++) {
            int k = k4 * 4 + kk;
            float4 b0 = *(const float4*)&ws[k * HID + c8 * 8];
            float4 b1 = *(const float4*)&ws[k * HID + c8 * 8 + 4];
#pragma unroll
            for (int q = 0; q < 4; q++) {
                float av = a[q][kk];
                acc[q][0] = fmaf(av, b0.x, acc[q][0]);
                acc[q][1] = fmaf(av, b0.y, acc[q][1]);
                acc[q][2] = fmaf(av, b0.z, acc[q][2]);
                acc[q][3] = fmaf(av, b0.w, acc[q][3]);
                acc[q][4] = fmaf(av, b1.x, acc[q][4]);
                acc[q][5] = fmaf(av, b1.y, acc[q][5]);
                acc[q][6] = fmaf(av, b1.z, acc[q][6]);
                acc[q][7] = fmaf(av, b1.w, acc[q][7]);
            }
        }
    }

    uint4* outv = (uint4*)g_hA;
#pragma unroll
    for (int q = 0; q < 4; q++) {
        int gr = row0 + r0 + q * 32;
        if (gr < n) outv[gr * 8 + c8] = pack8_half(acc[q]);
    }
}

// ---------------- aggregation ------------------------------------------------
// Half-warp per dst node (warp covers nodes 2w, 2w+1). 16 lanes x half4 (8B)
// = full 64-dim fp16 row; fp32 accumulation. 4x-unrolled (MLP=4 per half).
// FUSEPOOL: accumulate straight into per-graph embedding (layer 3).
template <int FUSEPOOL>
__global__ __launch_bounds__(256) void agg_kernel(const float* __restrict__ bias,
                                                  const int* __restrict__ batch,
                                                  int n, int relu) {
    int warp = (blockIdx.x * blockDim.x + threadIdx.x) >> 5;
    int lane = threadIdx.x & 31;
    int half = lane >> 4;
    int sl   = lane & 15;
    int node = warp * 2 + half;
    if (node >= n) return;

    const uint2* hv = (const uint2*)g_hA;     // 8B = 4 halves per lane
    float4 acc = make_float4(0.f, 0.f, 0.f, 0.f);

    int2 inf = g_info[node];
    int beg = inf.x;
    int end = beg + inf.y;
    int e = beg;
    for (; e + 3 < end; e += 4) {
        int2 p0 = g_edge[e];
        int2 p1 = g_edge[e + 1];
        int2 p2 = g_edge[e + 2];
        int2 p3 = g_edge[e + 3];
        uint2 u0 = hv[p0.x * 16 + sl];
        uint2 u1 = hv[p1.x * 16 + sl];
        uint2 u2 = hv[p2.x * 16 + sl];
        uint2 u3 = hv[p3.x * 16 + sl];
        float w0 = __int_as_float(p0.y);
        float w1 = __int_as_float(p1.y);
        float w2 = __int_as_float(p2.y);
        float w3 = __int_as_float(p3.y);
        float2 a0 = __half22float2(*(__half2*)&u0.x), b0 = __half22float2(*(__half2*)&u0.y);
        float2 a1 = __half22float2(*(__half2*)&u1.x), b1 = __half22float2(*(__half2*)&u1.y);
        float2 a2 = __half22float2(*(__half2*)&u2.x), b2 = __half22float2(*(__half2*)&u2.y);
        float2 a3 = __half22float2(*(__half2*)&u3.x), b3 = __half22float2(*(__half2*)&u3.y);
        acc.x = fmaf(w0, a0.x, fmaf(w1, a1.x, fmaf(w2, a2.x, fmaf(w3, a3.x, acc.x))));
        acc.y = fmaf(w0, a0.y, fmaf(w1, a1.y, fmaf(w2, a2.y, fmaf(w3, a3.y, acc.y))));
        acc.z = fmaf(w0, b0.x, fmaf(w1, b1.x, fmaf(w2, b2.x, fmaf(w3, b3.x, acc.z))));
        acc.w = fmaf(w0, b0.y, fmaf(w1, b1.y, fmaf(w2, b2.y, fmaf(w3, b3.y, acc.w))));
    }
    for (; e < end; e++) {
        int2 p0 = g_edge[e];
        uint2 u0 = hv[p0.x * 16 + sl];
        float w0 = __int_as_float(p0.y);
        float2 a0 = __half22float2(*(__half2*)&u0.x), b0 = __half22float2(*(__half2*)&u0.y);
        acc.x = fmaf(w0, a0.x, acc.x);
        acc.y = fmaf(w0, a0.y, acc.y);
        acc.z = fmaf(w0, b0.x, acc.z);
        acc.w = fmaf(w0, b0.y, acc.w);
    }

    float di = g_dinv[node];
    float sw = di * di;
    uint2 us = hv[node * 16 + sl];
    float2 sa = __half22float2(*(__half2*)&us.x), sb = __half22float2(*(__half2*)&us.y);
    float4 b  = ((const float4*)bias)[sl];
    acc.x = fmaf(sw, sa.x, acc.x) + b.x;
    acc.y = fmaf(sw, sa.y, acc.y) + b.y;
    acc.z = fmaf(sw, sb.x, acc.z) + b.z;
    acc.w = fmaf(sw, sb.y, acc.w) + b.w;
    if (relu) {
        acc.x = fmaxf(acc.x, 0.f);
        acc.y = fmaxf(acc.y, 0.f);
        acc.z = fmaxf(acc.z, 0.f);
        acc.w = fmaxf(acc.w, 0.f);
    }
    if (FUSEPOOL) {
        int g = batch[node];
        float* dst = &g_emb[g * HID + sl * 4];
        atomicAdd(dst + 0, acc.x);
        atomicAdd(dst + 1, acc.y);
        atomicAdd(dst + 2, acc.z);
        atomicAdd(dst + 3, acc.w);
    } else {
        ((float4*)g_hB)[node * 16 + sl] = acc;
    }
}

// ---------------- head: mean + centroid distances, min per class -------------
__global__ void head_kernel(const int* __restrict__ batch, int n,
                            const float* __restrict__ centroids,
                            const float* __restrict__ rbias,
                            float* __restrict__ out) {
    int g = blockIdx.x;
    int t = threadIdx.x;   // 64 threads
    __shared__ float e[HID];
    __shared__ float d[48];
    __shared__ float dpc[16];
    __shared__ float inv_cnt;

    if (t == 0) {
        int lo = 0, hi = n;
        while (lo < hi) { int m = (lo + hi) >> 1; if (batch[m] < g) lo = m + 1; else hi = m; }
        int a = lo;
        lo = 0; hi = n;
        while (lo < hi) { int m = (lo + hi) >> 1; if (batch[m] <= g) lo = m + 1; else hi = m; }
        int c = lo - a;
        inv_cnt = 1.0f / (float)(c > 1 ? c : 1);
    }
    __syncthreads();

    e[t] = g_emb[g * HID + t] * inv_cnt;
    __syncthreads();

    if (t < 48) {
        float acc = 0.f;
#pragma unroll
        for (int k = 0; k < HID; k++) {
            float df = e[k] - centroids[t * HID + k];
            acc = fmaf(df, df, acc);
        }
        d[t] = acc;
    }
    __syncthreads();
    if (t < 16) {
        float m = fminf(d[t * 3], fminf(d[t * 3 + 1], d[t * 3 + 2]));
        dpc[t] = m;
        out[g * 17 + t] = -m;
    }
    __syncthreads();
    if (t == 0) {
        float mm = dpc[0];
#pragma unroll
        for (int i = 1; i < 16; i++) mm = fminf(mm, dpc[i]);
        out[g * 17 + 16] = mm - rbias[0];
    }
}

// ---------------- launch -----------------------------------------------------
extern "C" void kernel_launch(void* const* d_in, const int* in_sizes, int n_in,
                              void* d_out, int out_size) {
    const float* x     = (const float*)d_in[0];
    const int*   ei    = (const int*)d_in[1];
    const int*   batch = (const int*)d_in[2];
    const float* W1    = (const float*)d_in[3];
    const float* b1    = (const float*)d_in[4];
    const float* W2    = (const float*)d_in[5];
    const float* b2    = (const float*)d_in[6];
    const float* W3    = (const float*)d_in[7];
    const float* b3    = (const float*)d_in[8];
    const float* cent  = (const float*)d_in[9];
    const float* rb    = (const float*)d_in[10];
    float* out = (float*)d_out;

    int n = in_sizes[0] / NFEAT;
    int E = in_sizes[1] / 2;
    int G = out_size / 17;

    const int smem128 = (64 * (NFEAT + 4) + NFEAT * HID) * (int)sizeof(float);
    const int smem64  = (128 * (HID + 4) + HID * HID) * (int)sizeof(float);

    static cudaStream_t s2;
    static cudaEvent_t ev_fork, ev_join;
    static void *p_deg, *p_fill, *p_emb, *p_total;
    static int init_done = 0;
    if (!init_done) {
        cudaFuncSetAttribute(gemm_kernel<NFEAT, 1>,
                             cudaFuncAttributeMaxDynamicSharedMemorySize, smem128);
        cudaFuncSetAttribute(gemm64_kernel,
                             cudaFuncAttributeMaxDynamicSharedMemorySize, smem64);
        cudaStreamCreateWithFlags(&s2, cudaStreamNonBlocking);
        cudaEventCreateWithFlags(&ev_fork, cudaEventDisableTiming);
        cudaEventCreateWithFlags(&ev_join, cudaEventDisableTiming);
        cudaGetSymbolAddress(&p_deg,   g_deg);
        cudaGetSymbolAddress(&p_fill,  g_fill);
        cudaGetSymbolAddress(&p_emb,   g_emb);
        cudaGetSymbolAddress(&p_total, g_total);
        init_done = 1;
    }

    int gemm_blocks   = (n + 63) / 64;
    int gemm64_blocks = (n + 127) / 128;
    int agg_blocks    = (n + 15) / 16;   // 8 warps/block, 2 nodes/warp

    // Fork: CSR build on s2 runs concurrently with layer-1 GEMM on stream 0.
    cudaEventRecord(ev_fork, 0);
    cudaStreamWaitEvent(s2, ev_fork, 0);

    cudaMemsetAsync(p_deg,   0, (size_t)n * 4, s2);
    cudaMemsetAsync(p_fill,  0, (size_t)n * 4, s2);
    cudaMemsetAsync(p_emb,   0, (size_t)G * HID * 4, s2);
    cudaMemsetAsync(p_total, 0, 4, s2);
    count_kernel<<<(E + 255) / 256, 256, 0, s2>>>(ei, E);
    alloc_kernel<<<(n + 255) / 256, 256, 0, s2>>>(n);
    fill_kernel<<<(E + 255) / 256, 256, 0, s2>>>(ei, E);
    cudaEventRecord(ev_join, s2);

    // layer-1 GEMM overlaps the CSR build
    gemm_kernel<NFEAT, 1><<<gemm_blocks, 256, smem128>>>(x, W1, n);

    // join: aggregation needs both the GEMM output and the CSR
    cudaStreamWaitEvent(0, ev_join, 0);
    agg_kernel<0><<<agg_blocks, 256>>>(b1, batch, n, 1);
    // layer 2
    gemm64_kernel<<<gemm64_blocks, 256, smem64>>>(W2, n);
    agg_kernel<0><<<agg_blocks, 256>>>(b2, batch, n, 1);
    // layer 3 (aggregation fused with mean-pool accumulation)
    gemm64_kernel<<<gemm64_blocks, 256, smem64>>>(W3, n);
    agg_kernel<1><<<agg_blocks, 256>>>(b3, batch, n, 0);

    // head
    head_kernel<<<G, 64>>>(batch, n, cent, rb, out);
}

// round 10
// speedup vs baseline: 3.5617x; 1.2019x over previous
#include <cuda_runtime.h>
#include <cuda_fp16.h>

#define NMAX 100000
#define EMAX 1600000
#define GMAX 1024
#define HID  64
#define NFEAT 128

// ---------------- scratch (device globals; no allocation allowed) ------------
__device__ __align__(16) int    g_deg[NMAX];
__device__ __align__(16) float  g_dinv[NMAX];
__device__ __align__(16) int2   g_info[NMAX];       // {edge range offset, edge count}
__device__ __align__(16) int    g_fill[NMAX];
__device__ __align__(16) int2   g_edge[EMAX];       // packed {src, wnorm bits}
__device__ __align__(16) __half g_hA[NMAX * HID];   // GEMM output (fp16 gather source)
__device__ __align__(16) float  g_hB[NMAX * HID];   // agg output / GEMM input (fp32)
__device__ __align__(16) float  g_emb[GMAX * HID];
__device__ int g_total;

// ---------------- setup ------------------------------------------------------
__global__ void count_kernel(const int* __restrict__ ei, int E) {
    int e = blockIdx.x * blockDim.x + threadIdx.x;
    if (e < E) atomicAdd(&g_deg[ei[E + e]], 1);
}

__global__ void alloc_kernel(int n) {
    int i = blockIdx.x * blockDim.x + threadIdx.x;
    if (i < n) {
        int d = g_deg[i];                 // real edge count (self-loop separate)
        g_dinv[i] = rsqrtf((float)(d + 1));
        int2 inf;
        inf.x = atomicAdd(&g_total, d);
        inf.y = d;
        g_info[i] = inf;
    }
}

__global__ void fill_kernel(const int* __restrict__ ei, int E) {
    int e = blockIdx.x * blockDim.x + threadIdx.x;
    if (e >= E) return;
    int s = ei[e];
    int d = ei[E + e];
    int pos = g_info[d].x + atomicAdd(&g_fill[d], 1);
    int2 p;
    p.x = s;
    p.y = __float_as_int(g_dinv[s] * g_dinv[d]);
    g_edge[pos] = p;
}

// ---------------- packed fp32x2 helpers (FFMA2 — ptxas won't emit from C++) --
__device__ __forceinline__ unsigned long long ffma2(unsigned long long a,
                                                    unsigned long long b,
                                                    unsigned long long c) {
    unsigned long long d;
    asm("fma.rn.f32x2 %0, %1, %2, %3;" : "=l"(d) : "l"(a), "l"(b), "l"(c));
    return d;
}
__device__ __forceinline__ unsigned long long pack2(float x, float y) {
    unsigned long long r;
    asm("mov.b64 %0, {%1, %2};" : "=l"(r) : "f"(x), "f"(y));
    return r;
}
__device__ __forceinline__ float2 unpack2(unsigned long long v) {
    float2 r;
    asm("mov.b64 {%0, %1}, %2;" : "=f"(r.x), "=f"(r.y) : "l"(v));
    return r;
}

// helper: 8 floats -> uint4 of half2s
__device__ __forceinline__ uint4 pack8_half(const float* a) {
    __half2 h0 = __floats2half2_rn(a[0], a[1]);
    __half2 h1 = __floats2half2_rn(a[2], a[3]);
    __half2 h2 = __floats2half2_rn(a[4], a[5]);
    __half2 h3 = __floats2half2_rn(a[6], a[7]);
    uint4 o;
    o.x = *(unsigned*)&h0; o.y = *(unsigned*)&h1;
    o.z = *(unsigned*)&h2; o.w = *(unsigned*)&h3;
    return o;
}

// ---------------- GEMM: g_hA(fp16)[n,64] = in[n,K] @ W[K,64] -----------------
// 128-row x 64-col block, 256 threads.
// Warp w owns columns w*8..w*8+7 (b-operand loads are warp-broadcast LDS —
// minimal L1TEX wavefronts). Lane owns 4 rows via transposed xs_T[k][row]
// (one LDS.128 feeds 4 rows at one k). Math in fma.rn.f32x2 (2 cols/instr).
// FROMARG selects input in DEVICE code only (host-side __device__ symbol args
// silently read the host shadow on GB300).
template <int K, int FROMARG>
__global__ __launch_bounds__(256) void gemm_kernel(const float* __restrict__ xin,
                                                   const float* __restrict__ W, int n) {
    constexpr int RP = 132;                   // padded row dim (16B-aligned rows)
    extern __shared__ float sm[];
    float* xsT = sm;                          // [K][RP]  (k-major, row minor)
    float* ws  = sm + K * RP;                 // [K][64]
    const float* in = FROMARG ? xin : (const float*)g_hB;

    int row0 = blockIdx.x * 128;

    // stage W
    for (int i = threadIdx.x; i < K * HID / 4; i += 256)
        ((float4*)ws)[i] = ((const float4*)W)[i];
    // stage x transposed: idx -> (r = idx&127, k4 = idx>>7)
    for (int idx = threadIdx.x; idx < 128 * (K / 4); idx += 256) {
        int r  = idx & 127;
        int k4 = idx >> 7;
        int gr = row0 + r;
        float4 v = make_float4(0.f, 0.f, 0.f, 0.f);
        if (gr < n) v = ((const float4*)in)[gr * (K / 4) + k4];
        xsT[(k4 * 4 + 0) * RP + r] = v.x;
        xsT[(k4 * 4 + 1) * RP + r] = v.y;
        xsT[(k4 * 4 + 2) * RP + r] = v.z;
        xsT[(k4 * 4 + 3) * RP + r] = v.w;
    }
    __syncthreads();

    int warp = threadIdx.x >> 5;              // 0..7 -> column octet
    int lane = threadIdx.x & 31;              // 4 rows: 4*lane..4*lane+3
    int c0 = warp * 8;

    unsigned long long acc[4][4];
#pragma unroll
    for (int q = 0; q < 4; q++)
#pragma unroll
        for (int j = 0; j < 4; j++) acc[q][j] = 0ull;

#pragma unroll 4
    for (int k = 0; k < K; k++) {
        // a: 4 rows at this k (one LDS.128)
        float4 a4 = *(const float4*)&xsT[k * RP + lane * 4];
        // b: 8 cols, warp-broadcast, reinterpreted as 4 packed f32x2
        ulonglong2 bb0 = *(const ulonglong2*)&ws[k * HID + c0];
        ulonglong2 bb1 = *(const ulonglong2*)&ws[k * HID + c0 + 4];
        unsigned long long ap0 = pack2(a4.x, a4.x);
        unsigned long long ap1 = pack2(a4.y, a4.y);
        unsigned long long ap2 = pack2(a4.z, a4.z);
        unsigned long long ap3 = pack2(a4.w, a4.w);
        acc[0][0] = ffma2(ap0, bb0.x, acc[0][0]);
        acc[0][1] = ffma2(ap0, bb0.y, acc[0][1]);
        acc[0][2] = ffma2(ap0, bb1.x, acc[0][2]);
        acc[0][3] = ffma2(ap0, bb1.y, acc[0][3]);
        acc[1][0] = ffma2(ap1, bb0.x, acc[1][0]);
        acc[1][1] = ffma2(ap1, bb0.y, acc[1][1]);
        acc[1][2] = ffma2(ap1, bb1.x, acc[1][2]);
        acc[1][3] = ffma2(ap1, bb1.y, acc[1][3]);
        acc[2][0] = ffma2(ap2, bb0.x, acc[2][0]);
        acc[2][1] = ffma2(ap2, bb0.y, acc[2][1]);
        acc[2][2] = ffma2(ap2, bb1.x, acc[2][2]);
        acc[2][3] = ffma2(ap2, bb1.y, acc[2][3]);
        acc[3][0] = ffma2(ap3, bb0.x, acc[3][0]);
        acc[3][1] = ffma2(ap3, bb0.y, acc[3][1]);
        acc[3][2] = ffma2(ap3, bb1.x, acc[3][2]);
        acc[3][3] = ffma2(ap3, bb1.y, acc[3][3]);
    }

    uint4* outv = (uint4*)g_hA;
#pragma unroll
    for (int q = 0; q < 4; q++) {
        int gr = row0 + lane * 4 + q;
        if (gr < n) {
            float v[8];
#pragma unroll
            for (int j = 0; j < 4; j++) {
                float2 p = unpack2(acc[q][j]);
                v[2 * j] = p.x; v[2 * j + 1] = p.y;
            }
            outv[gr * 8 + warp] = pack8_half(v);
        }
    }
}

// ---------------- aggregation ------------------------------------------------
// Half-warp per dst node (warp covers nodes 2w, 2w+1). 16 lanes x half4 (8B)
// = full 64-dim fp16 row; fp32 accumulation. 4x-unrolled (MLP=4 per half).
// FUSEPOOL: accumulate straight into per-graph embedding (layer 3).
template <int FUSEPOOL>
__global__ __launch_bounds__(256) void agg_kernel(const float* __restrict__ bias,
                                                  const int* __restrict__ batch,
                                                  int n, int relu) {
    int warp = (blockIdx.x * blockDim.x + threadIdx.x) >> 5;
    int lane = threadIdx.x & 31;
    int half = lane >> 4;
    int sl   = lane & 15;
    int node = warp * 2 + half;
    if (node >= n) return;

    const uint2* hv = (const uint2*)g_hA;     // 8B = 4 halves per lane
    float4 acc = make_float4(0.f, 0.f, 0.f, 0.f);

    int2 inf = g_info[node];
    int beg = inf.x;
    int end = beg + inf.y;
    int e = beg;
    for (; e + 3 < end; e += 4) {
        int2 p0 = g_edge[e];
        int2 p1 = g_edge[e + 1];
        int2 p2 = g_edge[e + 2];
        int2 p3 = g_edge[e + 3];
        uint2 u0 = hv[p0.x * 16 + sl];
        uint2 u1 = hv[p1.x * 16 + sl];
        uint2 u2 = hv[p2.x * 16 + sl];
        uint2 u3 = hv[p3.x * 16 + sl];
        float w0 = __int_as_float(p0.y);
        float w1 = __int_as_float(p1.y);
        float w2 = __int_as_float(p2.y);
        float w3 = __int_as_float(p3.y);
        float2 a0 = __half22float2(*(__half2*)&u0.x), b0 = __half22float2(*(__half2*)&u0.y);
        float2 a1 = __half22float2(*(__half2*)&u1.x), b1 = __half22float2(*(__half2*)&u1.y);
        float2 a2 = __half22float2(*(__half2*)&u2.x), b2 = __half22float2(*(__half2*)&u2.y);
        float2 a3 = __half22float2(*(__half2*)&u3.x), b3 = __half22float2(*(__half2*)&u3.y);
        acc.x = fmaf(w0, a0.x, fmaf(w1, a1.x, fmaf(w2, a2.x, fmaf(w3, a3.x, acc.x))));
        acc.y = fmaf(w0, a0.y, fmaf(w1, a1.y, fmaf(w2, a2.y, fmaf(w3, a3.y, acc.y))));
        acc.z = fmaf(w0, b0.x, fmaf(w1, b1.x, fmaf(w2, b2.x, fmaf(w3, b3.x, acc.z))));
        acc.w = fmaf(w0, b0.y, fmaf(w1, b1.y, fmaf(w2, b2.y, fmaf(w3, b3.y, acc.w))));
    }
    for (; e < end; e++) {
        int2 p0 = g_edge[e];
        uint2 u0 = hv[p0.x * 16 + sl];
        float w0 = __int_as_float(p0.y);
        float2 a0 = __half22float2(*(__half2*)&u0.x), b0 = __half22float2(*(__half2*)&u0.y);
        acc.x = fmaf(w0, a0.x, acc.x);
        acc.y = fmaf(w0, a0.y, acc.y);
        acc.z = fmaf(w0, b0.x, acc.z);
        acc.w = fmaf(w0, b0.y, acc.w);
    }

    float di = g_dinv[node];
    float sw = di * di;
    uint2 us = hv[node * 16 + sl];
    float2 sa = __half22float2(*(__half2*)&us.x), sb = __half22float2(*(__half2*)&us.y);
    float4 b  = ((const float4*)bias)[sl];
    acc.x = fmaf(sw, sa.x, acc.x) + b.x;
    acc.y = fmaf(sw, sa.y, acc.y) + b.y;
    acc.z = fmaf(sw, sb.x, acc.z) + b.z;
    acc.w = fmaf(sw, sb.y, acc.w) + b.w;
    if (relu) {
        acc.x = fmaxf(acc.x, 0.f);
        acc.y = fmaxf(acc.y, 0.f);
        acc.z = fmaxf(acc.z, 0.f);
        acc.w = fmaxf(acc.w, 0.f);
    }
    if (FUSEPOOL) {
        int g = batch[node];
        float* dst = &g_emb[g * HID + sl * 4];
        atomicAdd(dst + 0, acc.x);
        atomicAdd(dst + 1, acc.y);
        atomicAdd(dst + 2, acc.z);
        atomicAdd(dst + 3, acc.w);
    } else {
        ((float4*)g_hB)[node * 16 + sl] = acc;
    }
}

// ---------------- head: mean + centroid distances, min per class -------------
__global__ void head_kernel(const int* __restrict__ batch, int n,
                            const float* __restrict__ centroids,
                            const float* __restrict__ rbias,
                            float* __restrict__ out) {
    int g = blockIdx.x;
    int t = threadIdx.x;   // 64 threads
    __shared__ float e[HID];
    __shared__ float d[48];
    __shared__ float dpc[16];
    __shared__ float inv_cnt;

    if (t == 0) {
        int lo = 0, hi = n;
        while (lo < hi) { int m = (lo + hi) >> 1; if (batch[m] < g) lo = m + 1; else hi = m; }
        int a = lo;
        lo = 0; hi = n;
        while (lo < hi) { int m = (lo + hi) >> 1; if (batch[m] <= g) lo = m + 1; else hi = m; }
        int c = lo - a;
        inv_cnt = 1.0f / (float)(c > 1 ? c : 1);
    }
    __syncthreads();

    e[t] = g_emb[g * HID + t] * inv_cnt;
    __syncthreads();

    if (t < 48) {
        float acc = 0.f;
#pragma unroll
        for (int k = 0; k < HID; k++) {
            float df = e[k] - centroids[t * HID + k];
            acc = fmaf(df, df, acc);
        }
        d[t] = acc;
    }
    __syncthreads();
    if (t < 16) {
        float m = fminf(d[t * 3], fminf(d[t * 3 + 1], d[t * 3 + 2]));
        dpc[t] = m;
        out[g * 17 + t] = -m;
    }
    __syncthreads();
    if (t == 0) {
        float mm = dpc[0];
#pragma unroll
        for (int i = 1; i < 16; i++) mm = fminf(mm, dpc[i]);
        out[g * 17 + 16] = mm - rbias[0];
    }
}

// ---------------- launch -----------------------------------------------------
extern "C" void kernel_launch(void* const* d_in, const int* in_sizes, int n_in,
                              void* d_out, int out_size) {
    const float* x     = (const float*)d_in[0];
    const int*   ei    = (const int*)d_in[1];
    const int*   batch = (const int*)d_in[2];
    const float* W1    = (const float*)d_in[3];
    const float* b1    = (const float*)d_in[4];
    const float* W2    = (const float*)d_in[5];
    const float* b2    = (const float*)d_in[6];
    const float* W3    = (const float*)d_in[7];
    const float* b3    = (const float*)d_in[8];
    const float* cent  = (const float*)d_in[9];
    const float* rb    = (const float*)d_in[10];
    float* out = (float*)d_out;

    int n = in_sizes[0] / NFEAT;
    int E = in_sizes[1] / 2;
    int G = out_size / 17;

    const int smem128 = (NFEAT * 132 + NFEAT * HID) * (int)sizeof(float);  // ~99.6KB
    const int smem64  = (HID * 132 + HID * HID) * (int)sizeof(float);      // ~49.8KB

    static cudaStream_t s2;
    static cudaEvent_t ev_fork, ev_join;
    static void *p_deg, *p_fill, *p_emb, *p_total;
    static int init_done = 0;
    if (!init_done) {
        cudaFuncSetAttribute(gemm_kernel<NFEAT, 1>,
                             cudaFuncAttributeMaxDynamicSharedMemorySize, smem128);
        cudaFuncSetAttribute(gemm_kernel<HID, 0>,
                             cudaFuncAttributeMaxDynamicSharedMemorySize, smem64);
        cudaStreamCreateWithFlags(&s2, cudaStreamNonBlocking);
        cudaEventCreateWithFlags(&ev_fork, cudaEventDisableTiming);
        cudaEventCreateWithFlags(&ev_join, cudaEventDisableTiming);
        cudaGetSymbolAddress(&p_deg,   g_deg);
        cudaGetSymbolAddress(&p_fill,  g_fill);
        cudaGetSymbolAddress(&p_emb,   g_emb);
        cudaGetSymbolAddress(&p_total, g_total);
        init_done = 1;
    }

    int gemm_blocks = (n + 127) / 128;
    int agg_blocks  = (n + 15) / 16;   // 8 warps/block, 2 nodes/warp

    // Fork: CSR build on s2 runs concurrently with layer-1 GEMM on stream 0.
    cudaEventRecord(ev_fork, 0);
    cudaStreamWaitEvent(s2, ev_fork, 0);

    cudaMemsetAsync(p_deg,   0, (size_t)n * 4, s2);
    cudaMemsetAsync(p_fill,  0, (size_t)n * 4, s2);
    cudaMemsetAsync(p_emb,   0, (size_t)G * HID * 4, s2);
    cudaMemsetAsync(p_total, 0, 4, s2);
    count_kernel<<<(E + 255) / 256, 256, 0, s2>>>(ei, E);
    alloc_kernel<<<(n + 255) / 256, 256, 0, s2>>>(n);
    fill_kernel<<<(E + 255) / 256, 256, 0, s2>>>(ei, E);
    cudaEventRecord(ev_join, s2);

    // layer-1 GEMM overlaps the CSR build
    gemm_kernel<NFEAT, 1><<<gemm_blocks, 256, smem128>>>(x, W1, n);

    // join: aggregation needs both the GEMM output and the CSR
    cudaStreamWaitEvent(0, ev_join, 0);
    agg_kernel<0><<<agg_blocks, 256>>>(b1, batch, n, 1);
    // layer 2
    gemm_kernel<HID, 0><<<gemm_blocks, 256, smem64>>>(nullptr, W2, n);
    agg_kernel<0><<<agg_blocks, 256>>>(b2, batch, n, 1);
    // layer 3 (aggregation fused with mean-pool accumulation)
    gemm_kernel<HID, 0><<<gemm_blocks, 256, smem64>>>(nullptr, W3, n);
    agg_kernel<1><<<agg_blocks, 256>>>(b3, batch, n, 0);

    // head
    head_kernel<<<G, 64>>>(batch, n, cent, rb, out);
}

// round 11
// speedup vs baseline: 3.6031x; 1.0116x over previous
#include <cuda_runtime.h>
#include <cuda_fp16.h>

#define NMAX 100000
#define EMAX 1600000
#define GMAX 1024
#define HID  64
#define NFEAT 128

// ---------------- scratch (device globals; no allocation allowed) ------------
__device__ __align__(16) int    g_deg[NMAX];
__device__ __align__(16) float  g_dinv[NMAX];
__device__ __align__(16) int2   g_info[NMAX];       // {edge range offset, edge count}
__device__ __align__(16) int    g_fill[NMAX];
__device__ __align__(16) int2   g_edge[EMAX];       // packed {src, wnorm bits}
__device__ __align__(16) __half g_hA[NMAX * HID];   // GEMM output (fp16 gather source)
__device__ __align__(16) __half g_hB[NMAX * HID];   // agg output / GEMM input (fp16)
__device__ __align__(16) float  g_emb[GMAX * HID];
__device__ int g_total;

// ---------------- setup ------------------------------------------------------
__global__ void count_kernel(const int* __restrict__ ei, int E) {
    int e = blockIdx.x * blockDim.x + threadIdx.x;
    if (e < E) atomicAdd(&g_deg[ei[E + e]], 1);
}

__global__ void alloc_kernel(int n) {
    int i = blockIdx.x * blockDim.x + threadIdx.x;
    if (i < n) {
        int d = g_deg[i];                 // real edge count (self-loop separate)
        g_dinv[i] = rsqrtf((float)(d + 1));
        int2 inf;
        inf.x = atomicAdd(&g_total, d);
        inf.y = d;
        g_info[i] = inf;
    }
}

__global__ void fill_kernel(const int* __restrict__ ei, int E) {
    int e = blockIdx.x * blockDim.x + threadIdx.x;
    if (e >= E) return;
    int s = ei[e];
    int d = ei[E + e];
    int pos = g_info[d].x + atomicAdd(&g_fill[d], 1);
    int2 p;
    p.x = s;
    p.y = __float_as_int(g_dinv[s] * g_dinv[d]);
    g_edge[pos] = p;
}

// ---------------- packed fp32x2 helpers (FFMA2 — ptxas won't emit from C++) --
__device__ __forceinline__ unsigned long long ffma2(unsigned long long a,
                                                    unsigned long long b,
                                                    unsigned long long c) {
    unsigned long long d;
    asm("fma.rn.f32x2 %0, %1, %2, %3;" : "=l"(d) : "l"(a), "l"(b), "l"(c));
    return d;
}
__device__ __forceinline__ unsigned long long pack2(float x, float y) {
    unsigned long long r;
    asm("mov.b64 %0, {%1, %2};" : "=l"(r) : "f"(x), "f"(y));
    return r;
}
__device__ __forceinline__ float2 unpack2(unsigned long long v) {
    float2 r;
    asm("mov.b64 {%0, %1}, %2;" : "=f"(r.x), "=f"(r.y) : "l"(v));
    return r;
}

// helper: 8 floats -> uint4 of half2s
__device__ __forceinline__ uint4 pack8_half(const float* a) {
    __half2 h0 = __floats2half2_rn(a[0], a[1]);
    __half2 h1 = __floats2half2_rn(a[2], a[3]);
    __half2 h2 = __floats2half2_rn(a[4], a[5]);
    __half2 h3 = __floats2half2_rn(a[6], a[7]);
    uint4 o;
    o.x = *(unsigned*)&h0; o.y = *(unsigned*)&h1;
    o.z = *(unsigned*)&h2; o.w = *(unsigned*)&h3;
    return o;
}

// ---------------- GEMM: g_hA(fp16)[n,64] = in[n,K] @ W[K,64] -----------------
// 128-row x 64-col block, 256 threads. Warp w owns cols w*8..w*8+7 (b loads
// are warp-broadcast LDS). Lane owns 4 rows via transposed fp16 xsT[k][row]
// (one LDS.64 feeds 4 rows at one k). fp32x2 packed FMA accumulation.
// INHALF picks the input (x fp32 arg vs g_hB fp16) in DEVICE code only.
template <int K, int INHALF>
__global__ __launch_bounds__(256) void gemm_kernel(const float* __restrict__ xin,
                                                   const float* __restrict__ W, int n) {
    constexpr int RP = 132;                   // padded row dim (halves)
    extern __shared__ float sm[];
    __half* xsT = (__half*)sm;                // [K][RP] halves, k-major
    float*  ws  = sm + K * (RP / 2);          // [K][64] fp32
    int row0 = blockIdx.x * 128;

    // stage W (fp32)
    for (int i = threadIdx.x; i < K * HID / 4; i += 256)
        ((float4*)ws)[i] = ((const float4*)W)[i];

    // stage x transposed into fp16
    if (INHALF) {
        const __half* in = g_hB;
        for (int idx = threadIdx.x; idx < 128 * (K / 4); idx += 256) {
            int r  = idx & 127;
            int k4 = idx >> 7;
            int gr = row0 + r;
            uint2 v = make_uint2(0u, 0u);
            if (gr < n) v = ((const uint2*)in)[gr * (K / 4) + k4];
            __half2 h01 = *(__half2*)&v.x;
            __half2 h23 = *(__half2*)&v.y;
            xsT[(k4 * 4 + 0) * RP + r] = __low2half(h01);
            xsT[(k4 * 4 + 1) * RP + r] = __high2half(h01);
            xsT[(k4 * 4 + 2) * RP + r] = __low2half(h23);
            xsT[(k4 * 4 + 3) * RP + r] = __high2half(h23);
        }
    } else {
        const float* in = xin;
        for (int idx = threadIdx.x; idx < 128 * (K / 4); idx += 256) {
            int r  = idx & 127;
            int k4 = idx >> 7;
            int gr = row0 + r;
            float4 v = make_float4(0.f, 0.f, 0.f, 0.f);
            if (gr < n) v = ((const float4*)in)[gr * (K / 4) + k4];
            xsT[(k4 * 4 + 0) * RP + r] = __float2half_rn(v.x);
            xsT[(k4 * 4 + 1) * RP + r] = __float2half_rn(v.y);
            xsT[(k4 * 4 + 2) * RP + r] = __float2half_rn(v.z);
            xsT[(k4 * 4 + 3) * RP + r] = __float2half_rn(v.w);
        }
    }
    __syncthreads();

    int warp = threadIdx.x >> 5;              // 0..7 -> column octet
    int lane = threadIdx.x & 31;              // 4 rows: 4*lane..4*lane+3
    int c0 = warp * 8;

    unsigned long long acc[4][4];
#pragma unroll
    for (int q = 0; q < 4; q++)
#pragma unroll
        for (int j = 0; j < 4; j++) acc[q][j] = 0ull;

#pragma unroll 4
    for (int k = 0; k < K; k++) {
        // a: 4 rows at this k (one LDS.64 of 4 halves)
        uint2 ah = *(const uint2*)&xsT[k * RP + lane * 4];
        float2 f01 = __half22float2(*(__half2*)&ah.x);
        float2 f23 = __half22float2(*(__half2*)&ah.y);
        // b: 8 cols, warp-broadcast fp32, reinterpreted as 4 packed f32x2
        ulonglong2 bb0 = *(const ulonglong2*)&ws[k * HID + c0];
        ulonglong2 bb1 = *(const ulonglong2*)&ws[k * HID + c0 + 4];
        unsigned long long ap0 = pack2(f01.x, f01.x);
        unsigned long long ap1 = pack2(f01.y, f01.y);
        unsigned long long ap2 = pack2(f23.x, f23.x);
        unsigned long long ap3 = pack2(f23.y, f23.y);
        acc[0][0] = ffma2(ap0, bb0.x, acc[0][0]);
        acc[0][1] = ffma2(ap0, bb0.y, acc[0][1]);
        acc[0][2] = ffma2(ap0, bb1.x, acc[0][2]);
        acc[0][3] = ffma2(ap0, bb1.y, acc[0][3]);
        acc[1][0] = ffma2(ap1, bb0.x, acc[1][0]);
        acc[1][1] = ffma2(ap1, bb0.y, acc[1][1]);
        acc[1][2] = ffma2(ap1, bb1.x, acc[1][2]);
        acc[1][3] = ffma2(ap1, bb1.y, acc[1][3]);
        acc[2][0] = ffma2(ap2, bb0.x, acc[2][0]);
        acc[2][1] = ffma2(ap2, bb0.y, acc[2][1]);
        acc[2][2] = ffma2(ap2, bb1.x, acc[2][2]);
        acc[2][3] = ffma2(ap2, bb1.y, acc[2][3]);
        acc[3][0] = ffma2(ap3, bb0.x, acc[3][0]);
        acc[3][1] = ffma2(ap3, bb0.y, acc[3][1]);
        acc[3][2] = ffma2(ap3, bb1.x, acc[3][2]);
        acc[3][3] = ffma2(ap3, bb1.y, acc[3][3]);
    }

    uint4* outv = (uint4*)g_hA;
#pragma unroll
    for (int q = 0; q < 4; q++) {
        int gr = row0 + lane * 4 + q;
        if (gr < n) {
            float v[8];
#pragma unroll
            for (int j = 0; j < 4; j++) {
                float2 p = unpack2(acc[q][j]);
                v[2 * j] = p.x; v[2 * j + 1] = p.y;
            }
            outv[gr * 8 + warp] = pack8_half(v);
        }
    }
}

// ---------------- aggregation ------------------------------------------------
// Half-warp per dst node (warp covers nodes 2w, 2w+1). 16 lanes x half4 (8B)
// = full 64-dim fp16 row; fp32 accumulation. 8x-unrolled (MLP=8 per half).
// FUSEPOOL: accumulate straight into per-graph embedding (layer 3).
template <int FUSEPOOL>
__global__ __launch_bounds__(256) void agg_kernel(const float* __restrict__ bias,
                                                  const int* __restrict__ batch,
                                                  int n, int relu) {
    int warp = (blockIdx.x * blockDim.x + threadIdx.x) >> 5;
    int lane = threadIdx.x & 31;
    int half = lane >> 4;
    int sl   = lane & 15;
    int node = warp * 2 + half;
    if (node >= n) return;

    const uint2* hv = (const uint2*)g_hA;     // 8B = 4 halves per lane
    float4 acc = make_float4(0.f, 0.f, 0.f, 0.f);

    int2 inf = g_info[node];
    int beg = inf.x;
    int end = beg + inf.y;
    int e = beg;
    for (; e + 7 < end; e += 8) {
        int2 p[8];
        uint2 u[8];
#pragma unroll
        for (int j = 0; j < 8; j++) p[j] = g_edge[e + j];
#pragma unroll
        for (int j = 0; j < 8; j++) u[j] = hv[p[j].x * 16 + sl];
#pragma unroll
        for (int j = 0; j < 8; j++) {
            float w = __int_as_float(p[j].y);
            float2 a = __half22float2(*(__half2*)&u[j].x);
            float2 b = __half22float2(*(__half2*)&u[j].y);
            acc.x = fmaf(w, a.x, acc.x);
            acc.y = fmaf(w, a.y, acc.y);
            acc.z = fmaf(w, b.x, acc.z);
            acc.w = fmaf(w, b.y, acc.w);
        }
    }
    for (; e + 1 < end; e += 2) {
        int2 p0 = g_edge[e];
        int2 p1 = g_edge[e + 1];
        uint2 u0 = hv[p0.x * 16 + sl];
        uint2 u1 = hv[p1.x * 16 + sl];
        float w0 = __int_as_float(p0.y);
        float w1 = __int_as_float(p1.y);
        float2 a0 = __half22float2(*(__half2*)&u0.x), b0 = __half22float2(*(__half2*)&u0.y);
        float2 a1 = __half22float2(*(__half2*)&u1.x), b1 = __half22float2(*(__half2*)&u1.y);
        acc.x = fmaf(w0, a0.x, fmaf(w1, a1.x, acc.x));
        acc.y = fmaf(w0, a0.y, fmaf(w1, a1.y, acc.y));
        acc.z = fmaf(w0, b0.x, fmaf(w1, b1.x, acc.z));
        acc.w = fmaf(w0, b0.y, fmaf(w1, b1.y, acc.w));
    }
    if (e < end) {
        int2 p0 = g_edge[e];
        uint2 u0 = hv[p0.x * 16 + sl];
        float w0 = __int_as_float(p0.y);
        float2 a0 = __half22float2(*(__half2*)&u0.x), b0 = __half22float2(*(__half2*)&u0.y);
        acc.x = fmaf(w0, a0.x, acc.x);
        acc.y = fmaf(w0, a0.y, acc.y);
        acc.z = fmaf(w0, b0.x, acc.z);
        acc.w = fmaf(w0, b0.y, acc.w);
    }

    float di = g_dinv[node];
    float sw = di * di;
    uint2 us = hv[node * 16 + sl];
    float2 sa = __half22float2(*(__half2*)&us.x), sb = __half22float2(*(__half2*)&us.y);
    float4 b  = ((const float4*)bias)[sl];
    acc.x = fmaf(sw, sa.x, acc.x) + b.x;
    acc.y = fmaf(sw, sa.y, acc.y) + b.y;
    acc.z = fmaf(sw, sb.x, acc.z) + b.z;
    acc.w = fmaf(sw, sb.y, acc.w) + b.w;
    if (relu) {
        acc.x = fmaxf(acc.x, 0.f);
        acc.y = fmaxf(acc.y, 0.f);
        acc.z = fmaxf(acc.z, 0.f);
        acc.w = fmaxf(acc.w, 0.f);
    }
    if (FUSEPOOL) {
        int g = batch[node];
        float* dst = &g_emb[g * HID + sl * 4];
        atomicAdd(dst + 0, acc.x);
        atomicAdd(dst + 1, acc.y);
        atomicAdd(dst + 2, acc.z);
        atomicAdd(dst + 3, acc.w);
    } else {
        __half2 h0 = __floats2half2_rn(acc.x, acc.y);
        __half2 h1 = __floats2half2_rn(acc.z, acc.w);
        uint2 o;
        o.x = *(unsigned*)&h0; o.y = *(unsigned*)&h1;
        ((uint2*)g_hB)[node * 16 + sl] = o;
    }
}

// ---------------- head: mean + centroid distances, min per class -------------
__global__ void head_kernel(const int* __restrict__ batch, int n,
                            const float* __restrict__ centroids,
                            const float* __restrict__ rbias,
                            float* __restrict__ out) {
    int g = blockIdx.x;
    int t = threadIdx.x;   // 64 threads
    __shared__ float e[HID];
    __shared__ float d[48];
    __shared__ float dpc[16];
    __shared__ float inv_cnt;

    if (t == 0) {
        int lo = 0, hi = n;
        while (lo < hi) { int m = (lo + hi) >> 1; if (batch[m] < g) lo = m + 1; else hi = m; }
        int a = lo;
        lo = 0; hi = n;
        while (lo < hi) { int m = (lo + hi) >> 1; if (batch[m] <= g) lo = m + 1; else hi = m; }
        int c = lo - a;
        inv_cnt = 1.0f / (float)(c > 1 ? c : 1);
    }
    __syncthreads();

    e[t] = g_emb[g * HID + t] * inv_cnt;
    __syncthreads();

    if (t < 48) {
        float acc = 0.f;
#pragma unroll
        for (int k = 0; k < HID; k++) {
            float df = e[k] - centroids[t * HID + k];
            acc = fmaf(df, df, acc);
        }
        d[t] = acc;
    }
    __syncthreads();
    if (t < 16) {
        float m = fminf(d[t * 3], fminf(d[t * 3 + 1], d[t * 3 + 2]));
        dpc[t] = m;
        out[g * 17 + t] = -m;
    }
    __syncthreads();
    if (t == 0) {
        float mm = dpc[0];
#pragma unroll
        for (int i = 1; i < 16; i++) mm = fminf(mm, dpc[i]);
        out[g * 17 + 16] = mm - rbias[0];
    }
}

// ---------------- launch -----------------------------------------------------
extern "C" void kernel_launch(void* const* d_in, const int* in_sizes, int n_in,
                              void* d_out, int out_size) {
    const float* x     = (const float*)d_in[0];
    const int*   ei    = (const int*)d_in[1];
    const int*   batch = (const int*)d_in[2];
    const float* W1    = (const float*)d_in[3];
    const float* b1    = (const float*)d_in[4];
    const float* W2    = (const float*)d_in[5];
    const float* b2    = (const float*)d_in[6];
    const float* W3    = (const float*)d_in[7];
    const float* b3    = (const float*)d_in[8];
    const float* cent  = (const float*)d_in[9];
    const float* rb    = (const float*)d_in[10];
    float* out = (float*)d_out;

    int n = in_sizes[0] / NFEAT;
    int E = in_sizes[1] / 2;
    int G = out_size / 17;

    // smem: xsT fp16 [K][132] + ws fp32 [K][64]
    const int smem128 = (NFEAT * 66 + NFEAT * HID) * (int)sizeof(float);  // ~66.6KB
    const int smem64  = (HID * 66 + HID * HID) * (int)sizeof(float);      // ~33.3KB

    static cudaStream_t s2;
    static cudaEvent_t ev_fork, ev_join;
    static void *p_deg, *p_fill, *p_emb, *p_total;
    static int init_done = 0;
    if (!init_done) {
        cudaFuncSetAttribute(gemm_kernel<NFEAT, 0>,
                             cudaFuncAttributeMaxDynamicSharedMemorySize, smem128);
        cudaFuncSetAttribute(gemm_kernel<HID, 1>,
                             cudaFuncAttributeMaxDynamicSharedMemorySize, smem64);
        cudaStreamCreateWithFlags(&s2, cudaStreamNonBlocking);
        cudaEventCreateWithFlags(&ev_fork, cudaEventDisableTiming);
        cudaEventCreateWithFlags(&ev_join, cudaEventDisableTiming);
        cudaGetSymbolAddress(&p_deg,   g_deg);
        cudaGetSymbolAddress(&p_fill,  g_fill);
        cudaGetSymbolAddress(&p_emb,   g_emb);
        cudaGetSymbolAddress(&p_total, g_total);
        init_done = 1;
    }

    int gemm_blocks = (n + 127) / 128;
    int agg_blocks  = (n + 15) / 16;   // 8 warps/block, 2 nodes/warp

    // Fork: CSR build on s2 runs concurrently with layer-1 GEMM on stream 0.
    cudaEventRecord(ev_fork, 0);
    cudaStreamWaitEvent(s2, ev_fork, 0);

    cudaMemsetAsync(p_deg,   0, (size_t)n * 4, s2);
    cudaMemsetAsync(p_fill,  0, (size_t)n * 4, s2);
    cudaMemsetAsync(p_emb,   0, (size_t)G * HID * 4, s2);
    cudaMemsetAsync(p_total, 0, 4, s2);
    count_kernel<<<(E + 255) / 256, 256, 0, s2>>>(ei, E);
    alloc_kernel<<<(n + 255) / 256, 256, 0, s2>>>(n);
    fill_kernel<<<(E + 255) / 256, 256, 0, s2>>>(ei, E);
    cudaEventRecord(ev_join, s2);

    // layer-1 GEMM overlaps the CSR build
    gemm_kernel<NFEAT, 0><<<gemm_blocks, 256, smem128>>>(x, W1, n);

    // join: aggregation needs both the GEMM output and the CSR
    cudaStreamWaitEvent(0, ev_join, 0);
    agg_kernel<0><<<agg_blocks, 256>>>(b1, batch, n, 1);
    // layer 2
    gemm_kernel<HID, 1><<<gemm_blocks, 256, smem64>>>(nullptr, W2, n);
    agg_kernel<0><<<agg_blocks, 256>>>(b2, batch, n, 1);
    // layer 3 (aggregation fused with mean-pool accumulation)
    gemm_kernel<HID, 1><<<gemm_blocks, 256, smem64>>>(nullptr, W3, n);
    agg_kernel<1><<<agg_blocks, 256>>>(b3, batch, n, 0);

    // head
    head_kernel<<<G, 64>>>(batch, n, cent, rb, out);
}

// round 14
// speedup vs baseline: 4.5757x; 1.2699x over previous
#include <cuda_runtime.h>
#include <cuda_fp16.h>
#include <cstdint>

#define NMAX 100000
#define EMAX 1600000
#define GMAX 1024
#define HID  64
#define NFEAT 128

// ---------------- scratch (device globals; no allocation allowed) ------------
__device__ __align__(16) int    g_deg[NMAX];
__device__ __align__(16) float  g_dinv[NMAX];
__device__ __align__(16) int2   g_info[NMAX];       // {edge range offset, edge count}
__device__ __align__(16) int    g_fill[NMAX];
__device__ __align__(16) int2   g_edge[EMAX];       // packed {src, wnorm bits}
__device__ __align__(16) __half g_hA[NMAX * HID];   // GEMM output (fp16 gather source)
__device__ __align__(16) __half g_hB[NMAX * HID];   // agg output / GEMM input (fp16)
__device__ __align__(16) float  g_emb[GMAX * HID];
__device__ int g_total;

// ---------------- setup ------------------------------------------------------
__global__ void count_kernel(const int* __restrict__ ei, int E) {
    int e = blockIdx.x * blockDim.x + threadIdx.x;
    if (e < E) atomicAdd(&g_deg[ei[E + e]], 1);
}

__global__ void alloc_kernel(int n) {
    int i = blockIdx.x * blockDim.x + threadIdx.x;
    if (i < n) {
        int d = g_deg[i];                 // real edge count (self-loop separate)
        g_dinv[i] = rsqrtf((float)(d + 1));
        int2 inf;
        inf.x = atomicAdd(&g_total, d);
        inf.y = d;
        g_info[i] = inf;
    }
}

__global__ void fill_kernel(const int* __restrict__ ei, int E) {
    int e = blockIdx.x * blockDim.x + threadIdx.x;
    if (e >= E) return;
    int s = ei[e];
    int d = ei[E + e];
    int pos = g_info[d].x + atomicAdd(&g_fill[d], 1);
    int2 p;
    p.x = s;
    p.y = __float_as_int(g_dinv[s] * g_dinv[d]);
    g_edge[pos] = p;
}

// ---------------- mma helpers -------------------------------------------------
__device__ __forceinline__ unsigned smem_u32(const void* p) {
    return (unsigned)__cvta_generic_to_shared(p);
}
__device__ __forceinline__ void ldsm_x4(unsigned& r0, unsigned& r1, unsigned& r2,
                                        unsigned& r3, unsigned addr) {
    asm volatile("ldmatrix.sync.aligned.m8n8.x4.shared.b16 {%0,%1,%2,%3}, [%4];"
                 : "=r"(r0), "=r"(r1), "=r"(r2), "=r"(r3) : "r"(addr));
}
__device__ __forceinline__ void ldsm_x4_trans(unsigned& r0, unsigned& r1, unsigned& r2,
                                              unsigned& r3, unsigned addr) {
    asm volatile("ldmatrix.sync.aligned.m8n8.x4.trans.shared.b16 {%0,%1,%2,%3}, [%4];"
                 : "=r"(r0), "=r"(r1), "=r"(r2), "=r"(r3) : "r"(addr));
}
__device__ __forceinline__ void mma_16816(float* c, unsigned a0, unsigned a1,
                                          unsigned a2, unsigned a3,
                                          unsigned b0, unsigned b1) {
    asm volatile(
        "mma.sync.aligned.m16n8k16.row.col.f32.f16.f16.f32 "
        "{%0,%1,%2,%3}, {%4,%5,%6,%7}, {%8,%9}, {%0,%1,%2,%3};"
        : "+f"(c[0]), "+f"(c[1]), "+f"(c[2]), "+f"(c[3])
        : "r"(a0), "r"(a1), "r"(a2), "r"(a3), "r"(b0), "r"(b1));
}

// ---------------- GEMM (tensor cores): g_hA(fp16)[n,64] = in[n,K] @ W[K,64] --
// 128-row x 64-col block, 8 warps; warp w owns rows w*16..w*16+15, all 64 cols.
// A row-major fp16 smem (stride K+8), W fp16 smem (stride 72) — padded strides
// keep ldmatrix phases conflict-free. m16n8k16 HMMA, fp32 accumulators.
// INHALF picks the input (x fp32 arg vs g_hB fp16) in DEVICE code only
// (host-side __device__ symbol args silently read the host shadow on GB300).
template <int K, int INHALF>
__global__ __launch_bounds__(256) void gemm_kernel(const float* __restrict__ xin,
                                                   const float* __restrict__ W, int n) {
    constexpr int AP = K + 8;                 // halves per A row (272B / 144B)
    constexpr int WP = 72;                    // halves per W row (144B)
    extern __shared__ __half sm[];
    __half* As = sm;                          // [128][AP]
    __half* Ws = sm + 128 * AP;               // [K][WP]
    int row0 = blockIdx.x * 128;

    // stage W (fp32 -> fp16), 4 elems/thread/iter
    for (int i = threadIdx.x; i < K * 16; i += 256) {
        int r = i >> 4;
        int c = (i & 15) * 4;
        float4 v = ((const float4*)W)[i];
        __half2 h0 = __floats2half2_rn(v.x, v.y);
        __half2 h1 = __floats2half2_rn(v.z, v.w);
        uint2 o;
        o.x = *(unsigned*)&h0;
        o.y = *(unsigned*)&h1;
        *(uint2*)&Ws[r * WP + c] = o;
    }
    // stage A rows (row-major, no transpose)
    if (INHALF) {
        for (int i = threadIdx.x; i < 128 * (K / 4); i += 256) {
            int r = i / (K / 4);
            int c = (i % (K / 4)) * 4;
            int gr = row0 + r;
            uint2 v = make_uint2(0u, 0u);
            if (gr < n) v = ((const uint2*)g_hB)[gr * (K / 4) + (c >> 2)];
            *(uint2*)&As[r * AP + c] = v;
        }
    } else {
        for (int i = threadIdx.x; i < 128 * (K / 4); i += 256) {
            int r = i / (K / 4);
            int c = (i % (K / 4)) * 4;
            int gr = row0 + r;
            float4 v = make_float4(0.f, 0.f, 0.f, 0.f);
            if (gr < n) v = ((const float4*)xin)[gr * (K / 4) + (c >> 2)];
            __half2 h0 = __floats2half2_rn(v.x, v.y);
            __half2 h1 = __floats2half2_rn(v.z, v.w);
            uint2 o;
            o.x = *(unsigned*)&h0;
            o.y = *(unsigned*)&h1;
            *(uint2*)&As[r * AP + c] = o;
        }
    }
    __syncthreads();

    int warp = threadIdx.x >> 5;
    int lane = threadIdx.x & 31;
    int m0 = warp * 16;
    int gidx = lane & 7;
    int grp  = lane >> 3;                     // 0..3

    // A frags: grp0 rows m0+0..7 col 0 | grp1 rows m0+8..15 col 0
    //          grp2 rows m0+0..7 col 8 | grp3 rows m0+8..15 col 8
    int a_row  = m0 + gidx + ((grp & 1) << 3);
    int a_colh = (grp >> 1) << 3;
    unsigned a_base = smem_u32(&As[a_row * AP + a_colh]);
    // B frags (trans): grp0 k+0..7 at n | grp1 k+8..15 at n
    //                  grp2 k+0..7 at n+8 | grp3 k+8..15 at n+8
    int b_krow = gidx + ((grp & 1) << 3);
    int b_coln = (grp >> 1) << 3;
    unsigned b_base = smem_u32(&Ws[b_krow * WP + b_coln]);

    float acc[8][4];
#pragma unroll
    for (int t = 0; t < 8; t++) {
#pragma unroll
        for (int j = 0; j < 4; j++) acc[t][j] = 0.f;
    }

#pragma unroll
    for (int k = 0; k < K; k += 16) {
        unsigned a0, a1, a2, a3;
        ldsm_x4(a0, a1, a2, a3, a_base + k * 2);
#pragma unroll
        for (int t = 0; t < 4; t++) {         // each covers 2 n-tiles (16 cols)
            unsigned b0, b1, b2, b3;
            ldsm_x4_trans(b0, b1, b2, b3, b_base + (k * WP + t * 16) * 2);
            mma_16816(acc[2 * t],     a0, a1, a2, a3, b0, b1);
            mma_16816(acc[2 * t + 1], a0, a1, a2, a3, b2, b3);
        }
    }

    // write C frags as fp16: lane holds rows (lane>>2, +8), cols (lane&3)*2 per tile
    int cr = lane >> 2;
    int cc = (lane & 3) * 2;
    int gr0 = row0 + m0 + cr;
    int gr1 = gr0 + 8;
#pragma unroll
    for (int t = 0; t < 8; t++) {
        if (gr0 < n) {
            __half2 h = __floats2half2_rn(acc[t][0], acc[t][1]);
            *(unsigned*)&g_hA[gr0 * HID + t * 8 + cc] = *(unsigned*)&h;
        }
        if (gr1 < n) {
            __half2 h = __floats2half2_rn(acc[t][2], acc[t][3]);
            *(unsigned*)&g_hA[gr1 * HID + t * 8 + cc] = *(unsigned*)&h;
        }
    }
}

// ---------------- aggregation ------------------------------------------------
// Half-warp per dst node (warp covers nodes 2w, 2w+1). 16 lanes x half4 (8B)
// = full 64-dim fp16 row; fp32 accumulation. 8x-unrolled (MLP=8 per half).
// FUSEPOOL: accumulate straight into per-graph embedding (layer 3).
template <int FUSEPOOL>
__global__ __launch_bounds__(256) void agg_kernel(const float* __restrict__ bias,
                                                  const int* __restrict__ batch,
                                                  int n, int relu) {
    int warp = (blockIdx.x * blockDim.x + threadIdx.x) >> 5;
    int lane = threadIdx.x & 31;
    int half = lane >> 4;
    int sl   = lane & 15;
    int node = warp * 2 + half;
    if (node >= n) return;

    const uint2* hv = (const uint2*)g_hA;     // 8B = 4 halves per lane
    float4 acc = make_float4(0.f, 0.f, 0.f, 0.f);

    int2 inf = g_info[node];
    int beg = inf.x;
    int end = beg + inf.y;
    int e = beg;
    for (; e + 7 < end; e += 8) {
        int2 p[8];
        uint2 u[8];
#pragma unroll
        for (int j = 0; j < 8; j++) p[j] = g_edge[e + j];
#pragma unroll
        for (int j = 0; j < 8; j++) u[j] = hv[p[j].x * 16 + sl];
#pragma unroll
        for (int j = 0; j < 8; j++) {
            float w = __int_as_float(p[j].y);
            float2 a = __half22float2(*(__half2*)&u[j].x);
            float2 b = __half22float2(*(__half2*)&u[j].y);
            acc.x = fmaf(w, a.x, acc.x);
            acc.y = fmaf(w, a.y, acc.y);
            acc.z = fmaf(w, b.x, acc.z);
            acc.w = fmaf(w, b.y, acc.w);
        }
    }
    for (; e + 1 < end; e += 2) {
        int2 p0 = g_edge[e];
        int2 p1 = g_edge[e + 1];
        uint2 u0 = hv[p0.x * 16 + sl];
        uint2 u1 = hv[p1.x * 16 + sl];
        float w0 = __int_as_float(p0.y);
        float w1 = __int_as_float(p1.y);
        float2 a0 = __half22float2(*(__half2*)&u0.x);
        float2 b0 = __half22float2(*(__half2*)&u0.y);
        float2 a1 = __half22float2(*(__half2*)&u1.x);
        float2 b1 = __half22float2(*(__half2*)&u1.y);
        acc.x = fmaf(w0, a0.x, fmaf(w1, a1.x, acc.x));
        acc.y = fmaf(w0, a0.y, fmaf(w1, a1.y, acc.y));
        acc.z = fmaf(w0, b0.x, fmaf(w1, b1.x, acc.z));
        acc.w = fmaf(w0, b0.y, fmaf(w1, b1.y, acc.w));
    }
    if (e < end) {
        int2 p0 = g_edge[e];
        uint2 u0 = hv[p0.x * 16 + sl];
        float w0 = __int_as_float(p0.y);
        float2 a0 = __half22float2(*(__half2*)&u0.x);
        float2 b0 = __half22float2(*(__half2*)&u0.y);
        acc.x = fmaf(w0, a0.x, acc.x);
        acc.y = fmaf(w0, a0.y, acc.y);
        acc.z = fmaf(w0, b0.x, acc.z);
        acc.w = fmaf(w0, b0.y, acc.w);
    }

    float di = g_dinv[node];
    float sw = di * di;
    uint2 us = hv[node * 16 + sl];
    float2 sa = __half22float2(*(__half2*)&us.x);
    float2 sb = __half22float2(*(__half2*)&us.y);
    float4 b  = ((const float4*)bias)[sl];
    acc.x = fmaf(sw, sa.x, acc.x) + b.x;
    acc.y = fmaf(sw, sa.y, acc.y) + b.y;
    acc.z = fmaf(sw, sb.x, acc.z) + b.z;
    acc.w = fmaf(sw, sb.y, acc.w) + b.w;
    if (relu) {
        acc.x = fmaxf(acc.x, 0.f);
        acc.y = fmaxf(acc.y, 0.f);
        acc.z = fmaxf(acc.z, 0.f);
        acc.w = fmaxf(acc.w, 0.f);
    }
    if (FUSEPOOL) {
        int g = batch[node];
        float* dst = &g_emb[g * HID + sl * 4];
        atomicAdd(dst + 0, acc.x);
        atomicAdd(dst + 1, acc.y);
        atomicAdd(dst + 2, acc.z);
        atomicAdd(dst + 3, acc.w);
    } else {
        __half2 h0 = __floats2half2_rn(acc.x, acc.y);
        __half2 h1 = __floats2half2_rn(acc.z, acc.w);
        uint2 o;
        o.x = *(unsigned*)&h0;
        o.y = *(unsigned*)&h1;
        ((uint2*)g_hB)[node * 16 + sl] = o;
    }
}

// ---------------- head: mean + centroid distances, min per class -------------
__global__ void head_kernel(const int* __restrict__ batch, int n,
                            const float* __restrict__ centroids,
                            const float* __restrict__ rbias,
                            float* __restrict__ out) {
    int g = blockIdx.x;
    int t = threadIdx.x;   // 64 threads
    __shared__ float e[HID];
    __shared__ float d[48];
    __shared__ float dpc[16];
    __shared__ float inv_cnt;

    if (t == 0) {
        int lo = 0, hi = n;
        while (lo < hi) { int m = (lo + hi) >> 1; if (batch[m] < g) lo = m + 1; else hi = m; }
        int a = lo;
        lo = 0; hi = n;
        while (lo < hi) { int m = (lo + hi) >> 1; if (batch[m] <= g) lo = m + 1; else hi = m; }
        int c = lo - a;
        inv_cnt = 1.0f / (float)(c > 1 ? c : 1);
    }
    __syncthreads();

    e[t] = g_emb[g * HID + t] * inv_cnt;
    __syncthreads();

    if (t < 48) {
        float acc = 0.f;
#pragma unroll
        for (int k = 0; k < HID; k++) {
            float df = e[k] - centroids[t * HID + k];
            acc = fmaf(df, df, acc);
        }
        d[t] = acc;
    }
    __syncthreads();
    if (t < 16) {
        float m = fminf(d[t * 3], fminf(d[t * 3 + 1], d[t * 3 + 2]));
        dpc[t] = m;
        out[g * 17 + t] = -m;
    }
    __syncthreads();
    if (t == 0) {
        float mm = dpc[0];
#pragma unroll
        for (int i = 1; i < 16; i++) mm = fminf(mm, dpc[i]);
        out[g * 17 + 16] = mm - rbias[0];
    }
}

// ---------------- launch -----------------------------------------------------
extern "C" void kernel_launch(void* const* d_in, const int* in_sizes, int n_in,
                              void* d_out, int out_size) {
    const float* x     = (const float*)d_in[0];
    const int*   ei    = (const int*)d_in[1];
    const int*   batch = (const int*)d_in[2];
    const float* W1    = (const float*)d_in[3];
    const float* b1    = (const float*)d_in[4];
    const float* W2    = (const float*)d_in[5];
    const float* b2    = (const float*)d_in[6];
    const float* W3    = (const float*)d_in[7];
    const float* b3    = (const float*)d_in[8];
    const float* cent  = (const float*)d_in[9];
    const float* rb    = (const float*)d_in[10];
    float* out = (float*)d_out;

    int n = in_sizes[0] / NFEAT;
    int E = in_sizes[1] / 2;
    int G = out_size / 17;

    // smem: As [128][K+8] + Ws [K][72], halves
    const int smem128 = (128 * (NFEAT + 8) + NFEAT * 72) * 2;  // 52KB
    const int smem64  = (128 * (HID + 8)  + HID * 72) * 2;     // 27KB

    static cudaStream_t s2;
    static cudaEvent_t ev_fork, ev_join;
    static void *p_deg, *p_fill, *p_emb, *p_total;
    static int init_done = 0;
    if (!init_done) {
        cudaFuncSetAttribute(gemm_kernel<NFEAT, 0>,
                             cudaFuncAttributeMaxDynamicSharedMemorySize, smem128);
        cudaFuncSetAttribute(gemm_kernel<HID, 1>,
                             cudaFuncAttributeMaxDynamicSharedMemorySize, smem64);
        cudaStreamCreateWithFlags(&s2, cudaStreamNonBlocking);
        cudaEventCreateWithFlags(&ev_fork, cudaEventDisableTiming);
        cudaEventCreateWithFlags(&ev_join, cudaEventDisableTiming);
        cudaGetSymbolAddress(&p_deg,   g_deg);
        cudaGetSymbolAddress(&p_fill,  g_fill);
        cudaGetSymbolAddress(&p_emb,   g_emb);
        cudaGetSymbolAddress(&p_total, g_total);
        init_done = 1;
    }

    int gemm_blocks = (n + 127) / 128;
    int agg_blocks  = (n + 15) / 16;   // 8 warps/block, 2 nodes/warp

    // Fork: CSR build on s2 runs concurrently with layer-1 GEMM on stream 0.
    cudaEventRecord(ev_fork, 0);
    cudaStreamWaitEvent(s2, ev_fork, 0);

    cudaMemsetAsync(p_deg,   0, (size_t)n * 4, s2);
    cudaMemsetAsync(p_fill,  0, (size_t)n * 4, s2);
    cudaMemsetAsync(p_emb,   0, (size_t)G * HID * 4, s2);
    cudaMemsetAsync(p_total, 0, 4, s2);
    count_kernel<<<(E + 255) / 256, 256, 0, s2>>>(ei, E);
    alloc_kernel<<<(n + 255) / 256, 256, 0, s2>>>(n);
    fill_kernel<<<(E + 255) / 256, 256, 0, s2>>>(ei, E);
    cudaEventRecord(ev_join, s2);

    // layer-1 GEMM overlaps the CSR build
    gemm_kernel<NFEAT, 0><<<gemm_blocks, 256, smem128>>>(x, W1, n);

    // join: aggregation needs both the GEMM output and the CSR
    cudaStreamWaitEvent(0, ev_join, 0);
    agg_kernel<0><<<agg_blocks, 256>>>(b1, batch, n, 1);
    // layer 2
    gemm_kernel<HID, 1><<<gemm_blocks, 256, smem64>>>(nullptr, W2, n);
    agg_kernel<0><<<agg_blocks, 256>>>(b2, batch, n, 1);
    // layer 3 (aggregation fused with mean-pool accumulation)
    gemm_kernel<HID, 1><<<gemm_blocks, 256, smem64>>>(nullptr, W3, n);
    agg_kernel<1><<<agg_blocks, 256>>>(b3, batch, n, 0);

    // head
    head_kernel<<<G, 64>>>(batch, n, cent, rb, out);
}

// round 15
// speedup vs baseline: 4.5796x; 1.0009x over previous
#include <cuda_runtime.h>
#include <cuda_fp16.h>
#include <cstdint>

#define NMAX 100000
#define EMAX 1600000
#define GMAX 1024
#define HID  64
#define NFEAT 128

// ---------------- scratch (device globals; no allocation allowed) ------------
__device__ __align__(16) int      g_deg[NMAX];
__device__ __align__(16) float    g_dinv[NMAX];
__device__ __align__(16) int2     g_info[NMAX];      // {edge range offset, edge count}
__device__ __align__(16) int      g_fill[NMAX];
__device__ __align__(16) unsigned g_edge[EMAX];      // packed {src:17, fp16 wnorm:15}
__device__ __align__(16) __half   g_hA1[NMAX * HID]; // gemm1/gemm3 output
__device__ __align__(16) __half   g_hA2[NMAX * HID]; // gemm2 output
__device__ __align__(16) __half   g_hB[NMAX * HID];  // agg output / GEMM input
__device__ __align__(16) float    g_emb[GMAX * HID];
__device__ int g_total;

// ---------------- setup ------------------------------------------------------
__global__ void count_kernel(const int* __restrict__ ei, int E) {
    int e = blockIdx.x * blockDim.x + threadIdx.x;
    if (e < E) atomicAdd(&g_deg[ei[E + e]], 1);
}

__global__ void alloc_kernel(int n) {
    int i = blockIdx.x * blockDim.x + threadIdx.x;
    if (i < n) {
        int d = g_deg[i];                 // real edge count (self-loop separate)
        g_dinv[i] = rsqrtf((float)(d + 1));
        int2 inf;
        inf.x = atomicAdd(&g_total, d);
        inf.y = d;
        g_info[i] = inf;
    }
}

__global__ void fill_kernel(const int* __restrict__ ei, int E) {
    int e = blockIdx.x * blockDim.x + threadIdx.x;
    if (e >= E) return;
    int s = ei[e];
    int d = ei[E + e];
    int pos = g_info[d].x + atomicAdd(&g_fill[d], 1);
    float w = g_dinv[s] * g_dinv[d];                  // > 0 -> fp16 sign bit 0
    unsigned hb = (unsigned)__half_as_ushort(__float2half_rn(w));
    g_edge[pos] = ((unsigned)s << 15) | (hb & 0x7FFFu);
}

// ---------------- mma helpers -------------------------------------------------
__device__ __forceinline__ unsigned smem_u32(const void* p) {
    return (unsigned)__cvta_generic_to_shared(p);
}
__device__ __forceinline__ void ldsm_x4(unsigned& r0, unsigned& r1, unsigned& r2,
                                        unsigned& r3, unsigned addr) {
    asm volatile("ldmatrix.sync.aligned.m8n8.x4.shared.b16 {%0,%1,%2,%3}, [%4];"
                 : "=r"(r0), "=r"(r1), "=r"(r2), "=r"(r3) : "r"(addr));
}
__device__ __forceinline__ void ldsm_x4_trans(unsigned& r0, unsigned& r1, unsigned& r2,
                                              unsigned& r3, unsigned addr) {
    asm volatile("ldmatrix.sync.aligned.m8n8.x4.trans.shared.b16 {%0,%1,%2,%3}, [%4];"
                 : "=r"(r0), "=r"(r1), "=r"(r2), "=r"(r3) : "r"(addr));
}
__device__ __forceinline__ void mma_16816(float* c, unsigned a0, unsigned a1,
                                          unsigned a2, unsigned a3,
                                          unsigned b0, unsigned b1) {
    asm volatile(
        "mma.sync.aligned.m16n8k16.row.col.f32.f16.f16.f32 "
        "{%0,%1,%2,%3}, {%4,%5,%6,%7}, {%8,%9}, {%0,%1,%2,%3};"
        : "+f"(c[0]), "+f"(c[1]), "+f"(c[2]), "+f"(c[3])
        : "r"(a0), "r"(a1), "r"(a2), "r"(a3), "r"(b0), "r"(b1));
}

// ---------------- GEMM (tensor cores): out(fp16)[n,64] = in[n,K] @ W[K,64] ---
// 128-row x 64-col block, 8 warps; warp w owns rows w*16..w*16+15, all 64 cols.
// A row-major fp16 smem (stride K+8), W fp16 smem (stride 72). m16n8k16 HMMA.
// INHALF: input x(fp32 arg) vs g_hB(fp16). OUT2: write g_hA2 vs g_hA1.
// Buffer selection is DEVICE-side only (host-side __device__ symbol args
// silently read the host shadow on GB300). blk0 chunks rows for pipelining.
template <int K, int INHALF, int OUT2>
__global__ __launch_bounds__(256) void gemm_kernel(const float* __restrict__ xin,
                                                   const float* __restrict__ W,
                                                   int n, int blk0) {
    constexpr int AP = K + 8;
    constexpr int WP = 72;
    extern __shared__ __half sm[];
    __half* As = sm;                          // [128][AP]
    __half* Ws = sm + 128 * AP;               // [K][WP]
    int row0 = (blk0 + blockIdx.x) * 128;
    __half* out = OUT2 ? g_hA2 : g_hA1;

    for (int i = threadIdx.x; i < K * 16; i += 256) {
        int r = i >> 4;
        int c = (i & 15) * 4;
        float4 v = ((const float4*)W)[i];
        __half2 h0 = __floats2half2_rn(v.x, v.y);
        __half2 h1 = __floats2half2_rn(v.z, v.w);
        uint2 o;
        o.x = *(unsigned*)&h0;
        o.y = *(unsigned*)&h1;
        *(uint2*)&Ws[r * WP + c] = o;
    }
    if (INHALF) {
        for (int i = threadIdx.x; i < 128 * (K / 4); i += 256) {
            int r = i / (K / 4);
            int c = (i % (K / 4)) * 4;
            int gr = row0 + r;
            uint2 v = make_uint2(0u, 0u);
            if (gr < n) v = ((const uint2*)g_hB)[gr * (K / 4) + (c >> 2)];
            *(uint2*)&As[r * AP + c] = v;
        }
    } else {
        for (int i = threadIdx.x; i < 128 * (K / 4); i += 256) {
            int r = i / (K / 4);
            int c = (i % (K / 4)) * 4;
            int gr = row0 + r;
            float4 v = make_float4(0.f, 0.f, 0.f, 0.f);
            if (gr < n) v = ((const float4*)xin)[gr * (K / 4) + (c >> 2)];
            __half2 h0 = __floats2half2_rn(v.x, v.y);
            __half2 h1 = __floats2half2_rn(v.z, v.w);
            uint2 o;
            o.x = *(unsigned*)&h0;
            o.y = *(unsigned*)&h1;
            *(uint2*)&As[r * AP + c] = o;
        }
    }
    __syncthreads();

    int warp = threadIdx.x >> 5;
    int lane = threadIdx.x & 31;
    int m0 = warp * 16;
    int gidx = lane & 7;
    int grp  = lane >> 3;

    int a_row  = m0 + gidx + ((grp & 1) << 3);
    int a_colh = (grp >> 1) << 3;
    unsigned a_base = smem_u32(&As[a_row * AP + a_colh]);
    int b_krow = gidx + ((grp & 1) << 3);
    int b_coln = (grp >> 1) << 3;
    unsigned b_base = smem_u32(&Ws[b_krow * WP + b_coln]);

    float acc[8][4];
#pragma unroll
    for (int t = 0; t < 8; t++) {
#pragma unroll
        for (int j = 0; j < 4; j++) acc[t][j] = 0.f;
    }

#pragma unroll
    for (int k = 0; k < K; k += 16) {
        unsigned a0, a1, a2, a3;
        ldsm_x4(a0, a1, a2, a3, a_base + k * 2);
#pragma unroll
        for (int t = 0; t < 4; t++) {
            unsigned b0, b1, b2, b3;
            ldsm_x4_trans(b0, b1, b2, b3, b_base + (k * WP + t * 16) * 2);
            mma_16816(acc[2 * t],     a0, a1, a2, a3, b0, b1);
            mma_16816(acc[2 * t + 1], a0, a1, a2, a3, b2, b3);
        }
    }

    int cr = lane >> 2;
    int cc = (lane & 3) * 2;
    int gr0 = row0 + m0 + cr;
    int gr1 = gr0 + 8;
#pragma unroll
    for (int t = 0; t < 8; t++) {
        if (gr0 < n) {
            __half2 h = __floats2half2_rn(acc[t][0], acc[t][1]);
            *(unsigned*)&out[gr0 * HID + t * 8 + cc] = *(unsigned*)&h;
        }
        if (gr1 < n) {
            __half2 h = __floats2half2_rn(acc[t][2], acc[t][3]);
            *(unsigned*)&out[gr1 * HID + t * 8 + cc] = *(unsigned*)&h;
        }
    }
}

// ---------------- aggregation ------------------------------------------------
// Half-warp per dst node over [node0, node0+ncnt). 16 lanes x half4 (8B) =
// full 64-dim fp16 row; fp32 accumulation; 8x-unrolled (MLP=8 per half).
// SRC2: gather from g_hA2 vs g_hA1. FUSEPOOL: accumulate into g_emb.
template <int FUSEPOOL, int SRC2>
__global__ __launch_bounds__(256) void agg_kernel(const float* __restrict__ bias,
                                                  const int* __restrict__ batch,
                                                  int n, int relu,
                                                  int node0, int ncnt) {
    int warp = (blockIdx.x * blockDim.x + threadIdx.x) >> 5;
    int lane = threadIdx.x & 31;
    int half = lane >> 4;
    int sl   = lane & 15;
    int node = node0 + warp * 2 + half;
    if (node >= node0 + ncnt || node >= n) return;

    const uint2* hv = SRC2 ? (const uint2*)g_hA2 : (const uint2*)g_hA1;
    float4 acc = make_float4(0.f, 0.f, 0.f, 0.f);

    int2 inf = g_info[node];
    int beg = inf.x;
    int end = beg + inf.y;
    int e = beg;
    for (; e + 7 < end; e += 8) {
        unsigned p[8];
        uint2 u[8];
#pragma unroll
        for (int j = 0; j < 8; j++) p[j] = g_edge[e + j];
#pragma unroll
        for (int j = 0; j < 8; j++) u[j] = hv[(p[j] >> 15) * 16 + sl];
#pragma unroll
        for (int j = 0; j < 8; j++) {
            float w = __half2float(__ushort_as_half((unsigned short)(p[j] & 0x7FFFu)));
            float2 a = __half22float2(*(__half2*)&u[j].x);
            float2 b = __half22float2(*(__half2*)&u[j].y);
            acc.x = fmaf(w, a.x, acc.x);
            acc.y = fmaf(w, a.y, acc.y);
            acc.z = fmaf(w, b.x, acc.z);
            acc.w = fmaf(w, b.y, acc.w);
        }
    }
    for (; e < end; e++) {
        unsigned p0 = g_edge[e];
        uint2 u0 = hv[(p0 >> 15) * 16 + sl];
        float w0 = __half2float(__ushort_as_half((unsigned short)(p0 & 0x7FFFu)));
        float2 a0 = __half22float2(*(__half2*)&u0.x);
        float2 b0 = __half22float2(*(__half2*)&u0.y);
        acc.x = fmaf(w0, a0.x, acc.x);
        acc.y = fmaf(w0, a0.y, acc.y);
        acc.z = fmaf(w0, b0.x, acc.z);
        acc.w = fmaf(w0, b0.y, acc.w);
    }

    float di = g_dinv[node];
    float sw = di * di;
    uint2 us = hv[node * 16 + sl];
    float2 sa = __half22float2(*(__half2*)&us.x);
    float2 sb = __half22float2(*(__half2*)&us.y);
    float4 b  = ((const float4*)bias)[sl];
    acc.x = fmaf(sw, sa.x, acc.x) + b.x;
    acc.y = fmaf(sw, sa.y, acc.y) + b.y;
    acc.z = fmaf(sw, sb.x, acc.z) + b.z;
    acc.w = fmaf(sw, sb.y, acc.w) + b.w;
    if (relu) {
        acc.x = fmaxf(acc.x, 0.f);
        acc.y = fmaxf(acc.y, 0.f);
        acc.z = fmaxf(acc.z, 0.f);
        acc.w = fmaxf(acc.w, 0.f);
    }
    if (FUSEPOOL) {
        int g = batch[node];
        float* dst = &g_emb[g * HID + sl * 4];
        atomicAdd(dst + 0, acc.x);
        atomicAdd(dst + 1, acc.y);
        atomicAdd(dst + 2, acc.z);
        atomicAdd(dst + 3, acc.w);
    } else {
        __half2 h0 = __floats2half2_rn(acc.x, acc.y);
        __half2 h1 = __floats2half2_rn(acc.z, acc.w);
        uint2 o;
        o.x = *(unsigned*)&h0;
        o.y = *(unsigned*)&h1;
        ((uint2*)g_hB)[node * 16 + sl] = o;
    }
}

// ---------------- head: mean + centroid distances, min per class -------------
__global__ void head_kernel(const int* __restrict__ batch, int n,
                            const float* __restrict__ centroids,
                            const float* __restrict__ rbias,
                            float* __restrict__ out) {
    int g = blockIdx.x;
    int t = threadIdx.x;   // 64 threads
    __shared__ float e[HID];
    __shared__ float d[48];
    __shared__ float dpc[16];
    __shared__ float inv_cnt;

    if (t == 0) {
        int lo = 0, hi = n;
        while (lo < hi) { int m = (lo + hi) >> 1; if (batch[m] < g) lo = m + 1; else hi = m; }
        int a = lo;
        lo = 0; hi = n;
        while (lo < hi) { int m = (lo + hi) >> 1; if (batch[m] <= g) lo = m + 1; else hi = m; }
        int c = lo - a;
        inv_cnt = 1.0f / (float)(c > 1 ? c : 1);
    }
    __syncthreads();

    e[t] = g_emb[g * HID + t] * inv_cnt;
    __syncthreads();

    if (t < 48) {
        float acc = 0.f;
#pragma unroll
        for (int k = 0; k < HID; k++) {
            float df = e[k] - centroids[t * HID + k];
            acc = fmaf(df, df, acc);
        }
        d[t] = acc;
    }
    __syncthreads();
    if (t < 16) {
        float m = fminf(d[t * 3], fminf(d[t * 3 + 1], d[t * 3 + 2]));
        dpc[t] = m;
        out[g * 17 + t] = -m;
    }
    __syncthreads();
    if (t == 0) {
        float mm = dpc[0];
#pragma unroll
        for (int i = 1; i < 16; i++) mm = fminf(mm, dpc[i]);
        out[g * 17 + 16] = mm - rbias[0];
    }
}

// ---------------- launch -----------------------------------------------------
extern "C" void kernel_launch(void* const* d_in, const int* in_sizes, int n_in,
                              void* d_out, int out_size) {
    const float* x     = (const float*)d_in[0];
    const int*   ei    = (const int*)d_in[1];
    const int*   batch = (const int*)d_in[2];
    const float* W1    = (const float*)d_in[3];
    const float* b1    = (const float*)d_in[4];
    const float* W2    = (const float*)d_in[5];
    const float* b2    = (const float*)d_in[6];
    const float* W3    = (const float*)d_in[7];
    const float* b3    = (const float*)d_in[8];
    const float* cent  = (const float*)d_in[9];
    const float* rb    = (const float*)d_in[10];
    float* out = (float*)d_out;

    int n = in_sizes[0] / NFEAT;
    int E = in_sizes[1] / 2;
    int G = out_size / 17;

    const int smem128 = (128 * (NFEAT + 8) + NFEAT * 72) * 2;  // 52KB
    const int smem64  = (128 * (HID + 8)  + HID * 72) * 2;     // 27KB

    static cudaStream_t s2;
    static cudaEvent_t ev_fork, ev_csr, evA, evG2, evB, evG3;
    static void *p_deg, *p_fill, *p_emb, *p_total;
    static int init_done = 0;
    if (!init_done) {
        cudaFuncSetAttribute(gemm_kernel<NFEAT, 0, 0>,
                             cudaFuncAttributeMaxDynamicSharedMemorySize, smem128);
        cudaFuncSetAttribute(gemm_kernel<HID, 1, 1>,
                             cudaFuncAttributeMaxDynamicSharedMemorySize, smem64);
        cudaFuncSetAttribute(gemm_kernel<HID, 1, 0>,
                             cudaFuncAttributeMaxDynamicSharedMemorySize, smem64);
        cudaStreamCreateWithFlags(&s2, cudaStreamNonBlocking);
        cudaEventCreateWithFlags(&ev_fork, cudaEventDisableTiming);
        cudaEventCreateWithFlags(&ev_csr,  cudaEventDisableTiming);
        cudaEventCreateWithFlags(&evA,     cudaEventDisableTiming);
        cudaEventCreateWithFlags(&evG2,    cudaEventDisableTiming);
        cudaEventCreateWithFlags(&evB,     cudaEventDisableTiming);
        cudaEventCreateWithFlags(&evG3,    cudaEventDisableTiming);
        cudaGetSymbolAddress(&p_deg,   g_deg);
        cudaGetSymbolAddress(&p_fill,  g_fill);
        cudaGetSymbolAddress(&p_emb,   g_emb);
        cudaGetSymbolAddress(&p_total, g_total);
        init_done = 1;
    }

    int gemm_blocks = (n + 127) / 128;
    // chunk 0: multiple of 128 rows (gemm block) and even (agg warp pairing)
    int blk_c0 = (n / 2 + 127) / 128;
    if (blk_c0 > gemm_blocks) blk_c0 = gemm_blocks;
    int nc0 = blk_c0 * 128;
    if (nc0 > n) nc0 = n;
    int nc1 = n - nc0;
    int blk_c1 = gemm_blocks - blk_c0;
    int aggb_c0 = (nc0 + 15) / 16;
    int aggb_c1 = (nc1 + 15) / 16;
    int aggb_all = (n + 15) / 16;

    // Fork: CSR build on s2 runs concurrently with layer-1 GEMM on stream 0.
    cudaEventRecord(ev_fork, 0);
    cudaStreamWaitEvent(s2, ev_fork, 0);

    cudaMemsetAsync(p_deg,   0, (size_t)n * 4, s2);
    cudaMemsetAsync(p_fill,  0, (size_t)n * 4, s2);
    cudaMemsetAsync(p_emb,   0, (size_t)G * HID * 4, s2);
    cudaMemsetAsync(p_total, 0, 4, s2);
    count_kernel<<<(E + 255) / 256, 256, 0, s2>>>(ei, E);
    alloc_kernel<<<(n + 255) / 256, 256, 0, s2>>>(n);
    fill_kernel<<<(E + 255) / 256, 256, 0, s2>>>(ei, E);
    cudaEventRecord(ev_csr, s2);

    // layer-1 GEMM (x -> A1) overlaps the CSR build
    gemm_kernel<NFEAT, 0, 0><<<gemm_blocks, 256, smem128>>>(x, W1, n, 0);

    // agg1 needs CSR + gemm1
    cudaStreamWaitEvent(0, ev_csr, 0);
    // ---- layer 1 agg (A1 -> B), chunked; gemm2(c0) overlaps agg1(c1) -------
    agg_kernel<0, 0><<<aggb_c0, 256>>>(b1, batch, n, 1, 0, nc0);
    cudaEventRecord(evA, 0);
    cudaStreamWaitEvent(s2, evA, 0);
    gemm_kernel<HID, 1, 1><<<blk_c0, 256, smem64, s2>>>(nullptr, W2, n, 0);   // B->A2 c0
    cudaEventRecord(evG2, s2);
    if (nc1 > 0) {
        agg_kernel<0, 0><<<aggb_c1, 256>>>(b1, batch, n, 1, nc0, nc1);
        gemm_kernel<HID, 1, 1><<<blk_c1, 256, smem64>>>(nullptr, W2, n, blk_c0); // B->A2 c1
    }
    cudaStreamWaitEvent(0, evG2, 0);
    // ---- layer 2 agg (A2 -> B), chunked; gemm3(c0) overlaps agg2(c1) -------
    agg_kernel<0, 1><<<aggb_c0, 256>>>(b2, batch, n, 1, 0, nc0);
    cudaEventRecord(evB, 0);
    cudaStreamWaitEvent(s2, evB, 0);
    gemm_kernel<HID, 1, 0><<<blk_c0, 256, smem64, s2>>>(nullptr, W3, n, 0);   // B->A1 c0
    cudaEventRecord(evG3, s2);
    if (nc1 > 0) {
        agg_kernel<0, 1><<<aggb_c1, 256>>>(b2, batch, n, 1, nc0, nc1);
        gemm_kernel<HID, 1, 0><<<blk_c1, 256, smem64>>>(nullptr, W3, n, blk_c0); // B->A1 c1
    }
    cudaStreamWaitEvent(0, evG3, 0);
    // ---- layer 3 agg (A1) fused with mean-pool accumulation ----------------
    agg_kernel<1, 0><<<aggb_all, 256>>>(b3, batch, n, 0, 0, n);

    // head
    head_kernel<<<G, 64>>>(batch, n, cent, rb, out);
}